// round 2
// baseline (speedup 1.0000x reference)
#include <cuda_runtime.h>
#include <cuda_bf16.h>
#include <math.h>

// ---------------- static scratch (allocation-free) ----------------
#define UMAX 200000
__device__ int   g_winner[UMAX * 8];
__device__ int   g_selrows[UMAX];
__device__ int   g_bsum[256];
__device__ float g_hempty[64];
__device__ __align__(16) float g_flat[(size_t)UMAX * 512];
__device__ __align__(16) float g_z1[(size_t)UMAX * 256];
__device__ __align__(16) float g_stats1[512];   // sum[256] | sumsq[256]
__device__ __align__(16) float g_stats2[128];   // sum[64]  | sumsq[64]
__device__ __align__(16) float g_bn1sc[256];
__device__ __align__(16) float g_bn1sh[256];
__device__ __align__(16) float g_bn2sc[64];
__device__ __align__(16) float g_bn2sh[64];

// ---------------- init ----------------
__global__ void k_init(int nwin) {
    int i = blockIdx.x * blockDim.x + threadIdx.x;
    if (i < nwin) g_winner[i] = -1;
    if (i < 512)  g_stats1[i] = 0.f;
    if (i < 128)  g_stats2[i] = 0.f;
}

// ---------------- scatter: last-write-wins via max voxel index ----------------
__global__ void k_scatter(const int* __restrict__ coords, const int* __restrict__ inv, int Nv) {
    int i = blockIdx.x * blockDim.x + threadIdx.x;
    if (i < Nv) {
        int z = coords[(size_t)i * 4 + 1];
        int u = inv[i];
        atomicMax(&g_winner[(size_t)u * 8 + z], i);
    }
}

// ---------------- ordered compaction of rows with cnt>=2 ----------------
__global__ void k_count(const int* __restrict__ cnt, int U) {
    __shared__ int s[256];
    int base = blockIdx.x * 1024;
    int c = 0;
    for (int t = threadIdx.x; t < 1024; t += 256) {
        int u = base + t;
        if (u < U && cnt[u] >= 2) c++;
    }
    s[threadIdx.x] = c;
    __syncthreads();
    for (int o = 128; o > 0; o >>= 1) {
        if (threadIdx.x < o) s[threadIdx.x] += s[threadIdx.x + o];
        __syncthreads();
    }
    if (threadIdx.x == 0) g_bsum[blockIdx.x] = s[0];
}

__global__ void k_scan(int nb) {
    int acc = 0;
    for (int b = 0; b < nb; b++) { int v = g_bsum[b]; g_bsum[b] = acc; acc += v; }
}

__global__ void k_compact(const int* __restrict__ cnt, int U) {
    __shared__ int s[256];
    int tid = threadIdx.x;
    int base = blockIdx.x * 1024 + tid * 4;
    int flags[4]; int c = 0;
    for (int q = 0; q < 4; q++) {
        int u = base + q;
        flags[q] = (u < U && cnt[u] >= 2) ? 1 : 0;
        c += flags[q];
    }
    s[tid] = c;
    __syncthreads();
    for (int o = 1; o < 256; o <<= 1) {
        int v = (tid >= o) ? s[tid - o] : 0;
        __syncthreads();
        s[tid] += v;
        __syncthreads();
    }
    int off = g_bsum[blockIdx.x] + s[tid] - c;   // exclusive prefix for this thread
    for (int q = 0; q < 4; q++) {
        if (flags[q]) g_selrows[off++] = base + q;
    }
}

// ---------------- h for empty slots: relu(b1)@w2 + b2 ----------------
__global__ void k_hempty(const float* __restrict__ b1, const float* __restrict__ w2,
                         const float* __restrict__ b2) {
    int c = threadIdx.x;  // 64
    float acc = b2[c];
    for (int k = 0; k < 32; k++) acc += fmaxf(b1[k], 0.f) * w2[k * 64 + c];
    g_hempty[c] = acc;
}

// ---------------- fused per-row: slot MLP + CBAM + flatten ----------------
__global__ void __launch_bounds__(256)
k_rows(const float* __restrict__ vf,
       const float* __restrict__ w1, const float* __restrict__ b1,
       const float* __restrict__ w2g, const float* __restrict__ b2,
       const float* __restrict__ caw1, const float* __restrict__ caw2,
       const float* __restrict__ saconv, int M)
{
    __shared__ __align__(16) float shid[8][32];
    __shared__ __align__(16) float sx[512];                 // [c*8+z]
    __shared__ float sw1[160], sb1[32], sb2[64];
    __shared__ float scw1[512], scw2[512], sconv[14], she[64];
    __shared__ float sfeat[8][5];
    __shared__ int   swin[8];
    __shared__ float scm[64], scx[64];
    __shared__ float spart[64];
    __shared__ float smh[16];
    __shared__ float sca[64];
    __shared__ float szp[8][8], szq[8][8];
    __shared__ float szm[8], szx[8], ssa[8];

    int tid  = threadIdx.x;
    int z    = tid >> 5;    // warp id == bin
    int lane = tid & 31;

    for (int i = tid; i < 160; i += 256) sw1[i] = w1[i];
    if (tid < 32) sb1[tid] = b1[tid];
    if (tid < 64) sb2[tid] = b2[tid];
    for (int i = tid; i < 512; i += 256) scw1[i] = caw1[i];
    for (int i = tid; i < 512; i += 256) scw2[i] = caw2[i];
    if (tid < 14) sconv[tid] = saconv[tid];
    if (tid < 64) she[tid] = g_hempty[tid];

    // register-cache two w2 columns per thread (shared by all rows of this block)
    float w2c0[32], w2c1[32];
#pragma unroll
    for (int k = 0; k < 32; k++) {
        w2c0[k] = w2g[k * 64 + lane];
        w2c1[k] = w2g[k * 64 + lane + 32];
    }
    __syncthreads();

    for (int r = 0; r < 8; r++) {
        int j = blockIdx.x * 8 + r;
        if (j >= M) break;
        int u = g_selrows[j];
        if (tid < 8) swin[tid] = g_winner[(size_t)u * 8 + tid];
        __syncthreads();
        if (tid < 40) {
            int zz = tid / 5, f = tid % 5;
            int w = swin[zz];
            sfeat[zz][f] = (w >= 0) ? vf[(size_t)w * 5 + f] : 0.f;
        }
        __syncthreads();
        // hidden layer: thread (z, k)
        {
            int k = lane;
            float a = sb1[k];
#pragma unroll
            for (int f = 0; f < 5; f++) a += sfeat[z][f] * sw1[f * 32 + k];
            shid[z][k] = fmaxf(a, 0.f);
        }
        __syncthreads();
        // output layer: thread computes channels lane, lane+32 for its z
        {
            float h0, h1;
            if (swin[z] >= 0) {
                h0 = sb2[lane]; h1 = sb2[lane + 32];
#pragma unroll
                for (int k4 = 0; k4 < 32; k4 += 4) {
                    float4 hv = *(const float4*)&shid[z][k4];
                    h0 += hv.x * w2c0[k4] + hv.y * w2c0[k4 + 1] + hv.z * w2c0[k4 + 2] + hv.w * w2c0[k4 + 3];
                    h1 += hv.x * w2c1[k4] + hv.y * w2c1[k4 + 1] + hv.z * w2c1[k4 + 2] + hv.w * w2c1[k4 + 3];
                }
            } else { h0 = she[lane]; h1 = she[lane + 32]; }
            sx[lane * 8 + z]        = h0;
            sx[(lane + 32) * 8 + z] = h1;
        }
        __syncthreads();
        // channel stats over bins
        if (tid < 64) {
            float mn = 0.f, mx = -3.4e38f;
#pragma unroll
            for (int zz = 0; zz < 8; zz++) {
                float v = sx[tid * 8 + zz];
                mn += v; mx = fmaxf(mx, v);
            }
            scm[tid] = mn * 0.125f;
            scx[tid] = mx;
        }
        __syncthreads();
        // ca mlp hidden: 16 outputs x 4 partials
        if (tid < 64) {
            int o = tid >> 2, part = tid & 3;
            int vecsel = o >> 3, rr = o & 7;
            const float* v = vecsel ? scx : scm;
            float a = 0.f;
            int c0 = part * 16;
#pragma unroll
            for (int c = 0; c < 16; c++) a += v[c0 + c] * scw1[(c0 + c) * 8 + rr];
            spart[o * 4 + part] = a;
        }
        __syncthreads();
        if (tid < 16)
            smh[tid] = fmaxf(spart[tid * 4] + spart[tid * 4 + 1] + spart[tid * 4 + 2] + spart[tid * 4 + 3], 0.f);
        __syncthreads();
        if (tid < 64) {
            float a = 0.f;
#pragma unroll
            for (int rr = 0; rr < 8; rr++) a += (smh[rr] + smh[8 + rr]) * scw2[rr * 64 + tid];
            sca[tid] = 1.f / (1.f + expf(-a));
        }
        __syncthreads();
        sx[tid]       *= sca[tid >> 3];
        sx[tid + 256] *= sca[(tid + 256) >> 3];
        __syncthreads();
        // spatial stats: mean/max over channels per bin
        {
            int zz = lane & 7;
            int cg = z * 4 + (lane >> 3);   // 0..31 channel-pair groups
            float v0 = sx[(cg * 2) * 8 + zz];
            float v1 = sx[(cg * 2 + 1) * 8 + zz];
            float s = v0 + v1, m = fmaxf(v0, v1);
            s += __shfl_xor_sync(0xffffffffu, s, 8);
            m = fmaxf(m, __shfl_xor_sync(0xffffffffu, m, 8));
            s += __shfl_xor_sync(0xffffffffu, s, 16);
            m = fmaxf(m, __shfl_xor_sync(0xffffffffu, m, 16));
            if (lane < 8) { szp[z][lane] = s; szq[z][lane] = m; }
        }
        __syncthreads();
        if (tid < 8) {
            float s = 0.f, m = -3.4e38f;
#pragma unroll
            for (int w = 0; w < 8; w++) { s += szp[w][tid]; m = fmaxf(m, szq[w][tid]); }
            szm[tid] = s * (1.f / 64.f);
            szx[tid] = m;
        }
        __syncthreads();
        if (tid < 8) {
            float a = 0.f;
#pragma unroll
            for (int t = 0; t < 7; t++) {
                int p = tid + t - 3;
                if (p >= 0 && p < 8) a += szm[p] * sconv[t] + szx[p] * sconv[7 + t];
            }
            ssa[tid] = 1.f / (1.f + expf(-a));
        }
        __syncthreads();
        {
            size_t base = (size_t)j * 512;
            g_flat[base + tid]       = sx[tid]       * ssa[tid & 7];
            g_flat[base + tid + 256] = sx[tid + 256] * ssa[(tid + 256) & 7];
        }
        __syncthreads();
    }
}

// ---------------- GEMM1: z1 = flat(Mx512) @ W(512x256) ----------------
__global__ void __launch_bounds__(256)
k_gemm1(const float* __restrict__ W, int M) {
    __shared__ __align__(16) float As[8][128];
    __shared__ __align__(16) float Bs[8][128];
    int tid = threadIdx.x;
    int row0 = blockIdx.x * 128;
    int col0 = blockIdx.y * 128;
    int tx = tid & 15, ty = tid >> 4;
    float acc[8][8] = {};
    int a_row = tid >> 1, a_k = (tid & 1) * 4;
    int b_k = tid >> 5, b_c = (tid & 31) * 4;
    for (int k0 = 0; k0 < 512; k0 += 8) {
        float4 av = make_float4(0.f, 0.f, 0.f, 0.f);
        int gr = row0 + a_row;
        if (gr < M) av = *(const float4*)(g_flat + (size_t)gr * 512 + k0 + a_k);
        As[a_k + 0][a_row] = av.x; As[a_k + 1][a_row] = av.y;
        As[a_k + 2][a_row] = av.z; As[a_k + 3][a_row] = av.w;
        *(float4*)&Bs[b_k][b_c] = *(const float4*)(W + (size_t)(k0 + b_k) * 256 + col0 + b_c);
        __syncthreads();
#pragma unroll
        for (int k = 0; k < 8; k++) {
            float ar[8], br[8];
            *(float4*)(ar)     = *(float4*)&As[k][ty * 8];
            *(float4*)(ar + 4) = *(float4*)&As[k][ty * 8 + 4];
            *(float4*)(br)     = *(float4*)&Bs[k][tx * 8];
            *(float4*)(br + 4) = *(float4*)&Bs[k][tx * 8 + 4];
#pragma unroll
            for (int i = 0; i < 8; i++)
#pragma unroll
                for (int jj = 0; jj < 8; jj++) acc[i][jj] += ar[i] * br[jj];
        }
        __syncthreads();
    }
#pragma unroll
    for (int i = 0; i < 8; i++) {
        int gr = row0 + ty * 8 + i;
        if (gr < M) {
            float* dst = g_z1 + (size_t)gr * 256 + col0 + tx * 8;
            *(float4*)(dst)     = *(float4*)&acc[i][0];
            *(float4*)(dst + 4) = *(float4*)&acc[i][4];
        }
    }
}

// ---------------- column stats for bn1 ----------------
__global__ void k_stats1(int M) {
    int c = threadIdx.x;   // 256
    int base = blockIdx.x * 512;
    float s = 0.f, s2 = 0.f;
    int end = M - base; if (end > 512) end = 512;
    for (int r = 0; r < end; r++) {
        float v = g_z1[(size_t)(base + r) * 256 + c];
        s += v; s2 += v * v;
    }
    atomicAdd(&g_stats1[c], s);
    atomicAdd(&g_stats1[256 + c], s2);
}

__global__ void k_bnp(const float* __restrict__ g, const float* __restrict__ b,
                      int C, float invM, int which) {
    int c = blockIdx.x * blockDim.x + threadIdx.x;
    if (c < C) {
        const float* st = which ? g_stats2 : g_stats1;
        float* sc = which ? g_bn2sc : g_bn1sc;
        float* sh = which ? g_bn2sh : g_bn1sh;
        float mu  = st[c] * invM;
        float var = st[C + c] * invM - mu * mu;
        float s = g[c] * rsqrtf(var + 0.001f);
        sc[c] = s;
        sh[c] = b[c] - mu * s;
    }
}

// ---------------- GEMM2: out = relu(bn1(z1)) @ W2(256x64), bn1 folded into A-load ----------------
__global__ void __launch_bounds__(256)
k_gemm2(const float* __restrict__ W, float* __restrict__ out, int M) {
    __shared__ __align__(16) float As[16][128];
    __shared__ __align__(16) float Bs[16][64];
    int tid = threadIdx.x;
    int row0 = blockIdx.x * 128;
    int tx = tid & 15, ty = tid >> 4;
    float acc[8][4] = {};
    for (int k0 = 0; k0 < 256; k0 += 16) {
#pragma unroll
        for (int q = 0; q < 2; q++) {
            int idx = tid * 2 + q;
            int ar = idx >> 2, kq = (idx & 3) * 4;
            float4 av = make_float4(0.f, 0.f, 0.f, 0.f);
            int gr = row0 + ar;
            if (gr < M) av = *(const float4*)(g_z1 + (size_t)gr * 256 + k0 + kq);
            float4 sc = *(const float4*)(g_bn1sc + k0 + kq);
            float4 sh = *(const float4*)(g_bn1sh + k0 + kq);
            av.x = fmaxf(av.x * sc.x + sh.x, 0.f);
            av.y = fmaxf(av.y * sc.y + sh.y, 0.f);
            av.z = fmaxf(av.z * sc.z + sh.z, 0.f);
            av.w = fmaxf(av.w * sc.w + sh.w, 0.f);
            As[kq + 0][ar] = av.x; As[kq + 1][ar] = av.y;
            As[kq + 2][ar] = av.z; As[kq + 3][ar] = av.w;
        }
        {
            int b_k = tid >> 4, b_c = (tid & 15) * 4;
            *(float4*)&Bs[b_k][b_c] = *(const float4*)(W + (size_t)(k0 + b_k) * 64 + b_c);
        }
        __syncthreads();
#pragma unroll
        for (int k = 0; k < 16; k++) {
            float ar8[8], br4[4];
            *(float4*)(ar8)     = *(float4*)&As[k][ty * 8];
            *(float4*)(ar8 + 4) = *(float4*)&As[k][ty * 8 + 4];
            *(float4*)(br4)     = *(float4*)&Bs[k][tx * 4];
#pragma unroll
            for (int i = 0; i < 8; i++)
#pragma unroll
                for (int jj = 0; jj < 4; jj++) acc[i][jj] += ar8[i] * br4[jj];
        }
        __syncthreads();
    }
#pragma unroll
    for (int i = 0; i < 8; i++) {
        int gr = row0 + ty * 8 + i;
        if (gr < M) *(float4*)(out + (size_t)gr * 64 + tx * 4) = *(float4*)&acc[i][0];
    }
}

// ---------------- column stats for bn2 (on d_out holding raw z2) ----------------
__global__ void k_stats2(const float* __restrict__ z2, int M) {
    int c = threadIdx.x & 63, ro = threadIdx.x >> 6;
    int base = blockIdx.x * 1024;
    float s = 0.f, s2 = 0.f;
    for (int r = ro; r < 1024; r += 4) {
        int j = base + r;
        if (j >= M) break;
        float v = z2[(size_t)j * 64 + c];
        s += v; s2 += v * v;
    }
    atomicAdd(&g_stats2[c], s);
    atomicAdd(&g_stats2[64 + c], s2);
}

__global__ void k_final(float* __restrict__ out, int n) {
    int i = blockIdx.x * blockDim.x + threadIdx.x;
    if (i < n) {
        int c = i & 63;
        out[i] = fmaxf(out[i] * g_bn2sc[c] + g_bn2sh[c], 0.f);
    }
}

// ---------------- launcher ----------------
extern "C" void kernel_launch(void* const* d_in, const int* in_sizes, int n_in,
                              void* d_out, int out_size) {
    const float* vf      = (const float*)d_in[0];
    const int*   coords  = (const int*)d_in[1];
    const int*   inv     = (const int*)d_in[3];
    const int*   cnt     = (const int*)d_in[4];
    const float* up_w1   = (const float*)d_in[5];
    const float* up_b1   = (const float*)d_in[6];
    const float* up_w2   = (const float*)d_in[7];
    const float* up_b2   = (const float*)d_in[8];
    const float* ca_w1   = (const float*)d_in[9];
    const float* ca_w2   = (const float*)d_in[10];
    const float* sa_conv = (const float*)d_in[11];
    const float* bs_w1   = (const float*)d_in[12];
    const float* bn1_g   = (const float*)d_in[13];
    const float* bn1_b   = (const float*)d_in[14];
    const float* bs_w2   = (const float*)d_in[15];
    const float* bn2_g   = (const float*)d_in[16];
    const float* bn2_b   = (const float*)d_in[17];

    int Nv = in_sizes[0] / 5;
    int U  = in_sizes[2];
    int M  = out_size / 64;
    if (M <= 0) return;

    int nwin = U * 8;
    k_init<<<(nwin + 255) / 256, 256>>>(nwin);
    k_scatter<<<(Nv + 255) / 256, 256>>>(coords, inv, Nv);

    int NB = (U + 1023) / 1024;
    k_count<<<NB, 256>>>(cnt, U);
    k_scan<<<1, 1>>>(NB);
    k_compact<<<NB, 256>>>(cnt, U);

    k_hempty<<<1, 64>>>(up_b1, up_w2, up_b2);
    k_rows<<<(M + 7) / 8, 256>>>(vf, up_w1, up_b1, up_w2, up_b2,
                                 ca_w1, ca_w2, sa_conv, M);

    dim3 g1((M + 127) / 128, 2);
    k_gemm1<<<g1, 256>>>(bs_w1, M);
    k_stats1<<<(M + 511) / 512, 256>>>(M);
    k_bnp<<<1, 256>>>(bn1_g, bn1_b, 256, 1.f / (float)M, 0);

    k_gemm2<<<(M + 127) / 128, 256>>>(bs_w2, (float*)d_out, M);
    k_stats2<<<(M + 1023) / 1024, 256>>>((const float*)d_out, M);
    k_bnp<<<1, 64>>>(bn2_g, bn2_b, 64, 1.f / (float)M, 1);
    k_final<<<(M * 64 + 255) / 256, 256>>>((float*)d_out, M * 64);
}

// round 4
// speedup vs baseline: 1.3160x; 1.3160x over previous
#include <cuda_runtime.h>
#include <cuda_bf16.h>
#include <math.h>
#include <stdint.h>

// ---------------- static scratch (allocation-free) ----------------
#define UMAX 200000
__device__ int   g_winner[UMAX * 8];
__device__ int   g_selrows[UMAX];
__device__ int   g_bsum[256];
__device__ float g_hempty[64];
__device__ __align__(16) __nv_bfloat16 g_flat_hi[(size_t)UMAX * 512];
__device__ __align__(16) __nv_bfloat16 g_flat_lo[(size_t)UMAX * 512];
__device__ __align__(16) __nv_bfloat16 g_wt_hi[256 * 512];
__device__ __align__(16) __nv_bfloat16 g_wt_lo[256 * 512];
__device__ __align__(16) float g_z1[(size_t)UMAX * 256];
__device__ __align__(16) float g_stats1[512];   // sum[256] | sumsq[256]
__device__ __align__(16) float g_stats2[128];   // sum[64]  | sumsq[64]
__device__ __align__(16) float g_bn1sc[256];
__device__ __align__(16) float g_bn1sh[256];
__device__ __align__(16) float g_bn2sc[64];
__device__ __align__(16) float g_bn2sh[64];

__device__ __forceinline__ uint32_t smem_u32(const void* p) {
    uint32_t a;
    asm("{ .reg .u64 t; cvta.to.shared.u64 t, %1; cvt.u32.u64 %0, t; }" : "=r"(a) : "l"(p));
    return a;
}

// ---------------- init ----------------
__global__ void k_init(int nwin) {
    int i = blockIdx.x * blockDim.x + threadIdx.x;
    if (i < nwin) g_winner[i] = -1;
    if (i < 512)  g_stats1[i] = 0.f;
    if (i < 128)  g_stats2[i] = 0.f;
}

// ---------------- scatter: last-write-wins via max voxel index ----------------
__global__ void k_scatter(const int* __restrict__ coords, const int* __restrict__ inv, int Nv) {
    int i = blockIdx.x * blockDim.x + threadIdx.x;
    if (i < Nv) {
        int z = coords[(size_t)i * 4 + 1];
        int u = inv[i];
        atomicMax(&g_winner[(size_t)u * 8 + z], i);
    }
}

// ---------------- ordered compaction of rows with cnt>=2 ----------------
__global__ void k_count(const int* __restrict__ cnt, int U) {
    __shared__ int s[256];
    int base = blockIdx.x * 1024;
    int c = 0;
    for (int t = threadIdx.x; t < 1024; t += 256) {
        int u = base + t;
        if (u < U && cnt[u] >= 2) c++;
    }
    s[threadIdx.x] = c;
    __syncthreads();
    for (int o = 128; o > 0; o >>= 1) {
        if (threadIdx.x < o) s[threadIdx.x] += s[threadIdx.x + o];
        __syncthreads();
    }
    if (threadIdx.x == 0) g_bsum[blockIdx.x] = s[0];
}

__global__ void k_scan(int nb) {
    int acc = 0;
    for (int b = 0; b < nb; b++) { int v = g_bsum[b]; g_bsum[b] = acc; acc += v; }
}

__global__ void k_compact(const int* __restrict__ cnt, int U) {
    __shared__ int s[256];
    int tid = threadIdx.x;
    int base = blockIdx.x * 1024 + tid * 4;
    int flags[4]; int c = 0;
    for (int q = 0; q < 4; q++) {
        int u = base + q;
        flags[q] = (u < U && cnt[u] >= 2) ? 1 : 0;
        c += flags[q];
    }
    s[tid] = c;
    __syncthreads();
    for (int o = 1; o < 256; o <<= 1) {
        int v = (tid >= o) ? s[tid - o] : 0;
        __syncthreads();
        s[tid] += v;
        __syncthreads();
    }
    int off = g_bsum[blockIdx.x] + s[tid] - c;
    for (int q = 0; q < 4; q++) {
        if (flags[q]) g_selrows[off++] = base + q;
    }
}

// ---------------- h for empty slots: relu(b1)@w2 + b2 ----------------
__global__ void k_hempty(const float* __restrict__ b1, const float* __restrict__ w2,
                         const float* __restrict__ b2) {
    int c = threadIdx.x;  // 64
    float acc = b2[c];
    for (int k = 0; k < 32; k++) acc += fmaxf(b1[k], 0.f) * w2[k * 64 + c];
    g_hempty[c] = acc;
}

// ---------------- weight transpose + bf16 split: Wt[n][k] hi/lo ----------------
__global__ void k_prepw(const float* __restrict__ W) {
    int i = blockIdx.x * 256 + threadIdx.x;   // 131072 total
    int n = i >> 9, k = i & 511;
    float w = W[(size_t)k * 256 + n];
    __nv_bfloat16 hi = __float2bfloat16(w);
    float lo = w - __bfloat162float(hi);
    g_wt_hi[i] = hi;
    g_wt_lo[i] = __float2bfloat16(lo);
}

// ---------------- fused per-row: slot MLP + CBAM + flatten (emits bf16 hi/lo) ----------------
__global__ void __launch_bounds__(256)
k_rows(const float* __restrict__ vf,
       const float* __restrict__ w1, const float* __restrict__ b1,
       const float* __restrict__ w2g, const float* __restrict__ b2,
       const float* __restrict__ caw1, const float* __restrict__ caw2,
       const float* __restrict__ saconv, int M)
{
    __shared__ __align__(16) float shid[8][32];
    __shared__ __align__(16) float sx[512];                 // [c*8+z]
    __shared__ float sw1[160], sb1[32], sb2[64];
    __shared__ float scw1[512], scw2[512], sconv[14], she[64];
    __shared__ float sfeat[8][5];
    __shared__ int   swin[8];
    __shared__ float scm[64], scx[64];
    __shared__ float spart[64];
    __shared__ float smh[16];
    __shared__ float sca[64];
    __shared__ float szp[8][8], szq[8][8];
    __shared__ float szm[8], szx[8], ssa[8];

    int tid  = threadIdx.x;
    int z    = tid >> 5;
    int lane = tid & 31;

    for (int i = tid; i < 160; i += 256) sw1[i] = w1[i];
    if (tid < 32) sb1[tid] = b1[tid];
    if (tid < 64) sb2[tid] = b2[tid];
    for (int i = tid; i < 512; i += 256) scw1[i] = caw1[i];
    for (int i = tid; i < 512; i += 256) scw2[i] = caw2[i];
    if (tid < 14) sconv[tid] = saconv[tid];
    if (tid < 64) she[tid] = g_hempty[tid];

    float w2c0[32], w2c1[32];
#pragma unroll
    for (int k = 0; k < 32; k++) {
        w2c0[k] = w2g[k * 64 + lane];
        w2c1[k] = w2g[k * 64 + lane + 32];
    }
    __syncthreads();

    for (int r = 0; r < 8; r++) {
        int j = blockIdx.x * 8 + r;
        if (j >= M) break;
        int u = g_selrows[j];
        if (tid < 8) swin[tid] = g_winner[(size_t)u * 8 + tid];
        __syncthreads();
        if (tid < 40) {
            int zz = tid / 5, f = tid % 5;
            int w = swin[zz];
            sfeat[zz][f] = (w >= 0) ? vf[(size_t)w * 5 + f] : 0.f;
        }
        __syncthreads();
        {
            int k = lane;
            float a = sb1[k];
#pragma unroll
            for (int f = 0; f < 5; f++) a += sfeat[z][f] * sw1[f * 32 + k];
            shid[z][k] = fmaxf(a, 0.f);
        }
        __syncthreads();
        {
            float h0, h1;
            if (swin[z] >= 0) {
                h0 = sb2[lane]; h1 = sb2[lane + 32];
#pragma unroll
                for (int k4 = 0; k4 < 32; k4 += 4) {
                    float4 hv = *(const float4*)&shid[z][k4];
                    h0 += hv.x * w2c0[k4] + hv.y * w2c0[k4 + 1] + hv.z * w2c0[k4 + 2] + hv.w * w2c0[k4 + 3];
                    h1 += hv.x * w2c1[k4] + hv.y * w2c1[k4 + 1] + hv.z * w2c1[k4 + 2] + hv.w * w2c1[k4 + 3];
                }
            } else { h0 = she[lane]; h1 = she[lane + 32]; }
            sx[lane * 8 + z]        = h0;
            sx[(lane + 32) * 8 + z] = h1;
        }
        __syncthreads();
        if (tid < 64) {
            float mn = 0.f, mx = -3.4e38f;
#pragma unroll
            for (int zz = 0; zz < 8; zz++) {
                float v = sx[tid * 8 + zz];
                mn += v; mx = fmaxf(mx, v);
            }
            scm[tid] = mn * 0.125f;
            scx[tid] = mx;
        }
        __syncthreads();
        if (tid < 64) {
            int o = tid >> 2, part = tid & 3;
            int vecsel = o >> 3, rr = o & 7;
            const float* v = vecsel ? scx : scm;
            float a = 0.f;
            int c0 = part * 16;
#pragma unroll
            for (int c = 0; c < 16; c++) a += v[c0 + c] * scw1[(c0 + c) * 8 + rr];
            spart[o * 4 + part] = a;
        }
        __syncthreads();
        if (tid < 16)
            smh[tid] = fmaxf(spart[tid * 4] + spart[tid * 4 + 1] + spart[tid * 4 + 2] + spart[tid * 4 + 3], 0.f);
        __syncthreads();
        if (tid < 64) {
            float a = 0.f;
#pragma unroll
            for (int rr = 0; rr < 8; rr++) a += (smh[rr] + smh[8 + rr]) * scw2[rr * 64 + tid];
            sca[tid] = 1.f / (1.f + expf(-a));
        }
        __syncthreads();
        sx[tid]       *= sca[tid >> 3];
        sx[tid + 256] *= sca[(tid + 256) >> 3];
        __syncthreads();
        {
            int zz = lane & 7;
            int cg = z * 4 + (lane >> 3);
            float v0 = sx[(cg * 2) * 8 + zz];
            float v1 = sx[(cg * 2 + 1) * 8 + zz];
            float s = v0 + v1, m = fmaxf(v0, v1);
            s += __shfl_xor_sync(0xffffffffu, s, 8);
            m = fmaxf(m, __shfl_xor_sync(0xffffffffu, m, 8));
            s += __shfl_xor_sync(0xffffffffu, s, 16);
            m = fmaxf(m, __shfl_xor_sync(0xffffffffu, m, 16));
            if (lane < 8) { szp[z][lane] = s; szq[z][lane] = m; }
        }
        __syncthreads();
        if (tid < 8) {
            float s = 0.f, m = -3.4e38f;
#pragma unroll
            for (int w = 0; w < 8; w++) { s += szp[w][tid]; m = fmaxf(m, szq[w][tid]); }
            szm[tid] = s * (1.f / 64.f);
            szx[tid] = m;
        }
        __syncthreads();
        if (tid < 8) {
            float a = 0.f;
#pragma unroll
            for (int t = 0; t < 7; t++) {
                int p = tid + t - 3;
                if (p >= 0 && p < 8) a += szm[p] * sconv[t] + szx[p] * sconv[7 + t];
            }
            ssa[tid] = 1.f / (1.f + expf(-a));
        }
        __syncthreads();
        {
            size_t base = (size_t)j * 512;
#pragma unroll
            for (int q = 0; q < 2; q++) {
                int idx = tid + q * 256;
                float v = sx[idx] * ssa[idx & 7];
                __nv_bfloat16 hi = __float2bfloat16(v);
                float lo = v - __bfloat162float(hi);
                g_flat_hi[base + idx] = hi;
                g_flat_lo[base + idx] = __float2bfloat16(lo);
            }
        }
        __syncthreads();
    }
}

// ---------------- GEMM1 (mma.sync bf16 hi/lo split): z1 = flat(Mx512) @ W(512x256) ----------------
// block tile 128x128, K chunks of 64, 2-stage cp.async pipeline, smem pitch 72 elems (144B)
#define G1_PITCHB  144                 // bytes per smem row (72 bf16)
#define G1_A_HI    0
#define G1_A_LO    18432
#define G1_B_HI    36864
#define G1_B_LO    55296
#define G1_STAGE   73728

#define LDSM4(R0, R1, R2, R3, ADDR) \
    asm volatile("ldmatrix.sync.aligned.m8n8.x4.shared.b16 {%0,%1,%2,%3}, [%4];" \
                 : "=r"(R0), "=r"(R1), "=r"(R2), "=r"(R3) : "r"(ADDR))

#define MMA16816(D, A, B) \
    asm volatile("mma.sync.aligned.m16n8k16.row.col.f32.bf16.bf16.f32 " \
                 "{%0,%1,%2,%3}, {%4,%5,%6,%7}, {%8,%9}, {%0,%1,%2,%3};" \
                 : "+f"((D)[0]), "+f"((D)[1]), "+f"((D)[2]), "+f"((D)[3]) \
                 : "r"((A)[0]), "r"((A)[1]), "r"((A)[2]), "r"((A)[3]), \
                   "r"((B)[0]), "r"((B)[1]))

__device__ __forceinline__ void cp16(uint32_t saddr, const void* gaddr, uint32_t sz) {
    asm volatile("cp.async.cg.shared.global [%0], [%1], 16, %2;"
                 :: "r"(saddr), "l"(gaddr), "r"(sz));
}

__global__ void __launch_bounds__(256, 1)
k_gemm1_mma(int M) {
    extern __shared__ __align__(16) char dsm[];
    uint32_t sbase = smem_u32(dsm);

    int tid  = threadIdx.x;
    int lane = tid & 31;
    int wid  = tid >> 5;
    int wm = wid & 1;        // 2 m-warps (64 rows each)
    int wn = wid >> 1;       // 4 n-warps (32 cols each)
    int row0 = blockIdx.x * 128;
    int col0 = blockIdx.y * 128;

    // per-thread load indices (A and B use same pattern)
    int li_r  = tid >> 3;          // 0..31  (row step 32 per iter)
    int li_c8 = tid & 7;           // 8-elem group within 64

    float acc[4][4][4] = {};

    // ---- chunk loader (cp.async) ----
    auto load_chunk = [&](int c) {
        uint32_t st = sbase + (uint32_t)(c & 1) * G1_STAGE;
#pragma unroll
        for (int it = 0; it < 4; it++) {
            int r = li_r + it * 32;
            int gr = row0 + r;
            uint32_t soff = (uint32_t)(r * G1_PITCHB + li_c8 * 16);
            size_t goff = (size_t)gr * 512 + c * 64 + li_c8 * 8;
            uint32_t sz = (gr < M) ? 16u : 0u;
            cp16(st + G1_A_HI + soff, g_flat_hi + goff, sz);
            cp16(st + G1_A_LO + soff, g_flat_lo + goff, sz);
            int n = col0 + r;
            size_t boff = (size_t)n * 512 + c * 64 + li_c8 * 8;
            cp16(st + G1_B_HI + soff, g_wt_hi + boff, 16u);
            cp16(st + G1_B_LO + soff, g_wt_lo + boff, 16u);
        }
        asm volatile("cp.async.commit_group;");
    };

    load_chunk(0);

    // per-thread ldmatrix address components
    uint32_t aRow  = (uint32_t)(wm * 64 + (lane & 15));
    uint32_t aColB = (uint32_t)((lane >> 4) * 16);            // bytes
    uint32_t bRow  = (uint32_t)(wn * 32 + ((lane >> 4) & 1) * 8 + (lane & 7));
    uint32_t bColB = (uint32_t)(((lane >> 3) & 1) * 16);      // bytes

    for (int c = 0; c < 8; c++) {
        if (c < 7) load_chunk(c + 1);
        if (c < 7) { asm volatile("cp.async.wait_group 1;"); }
        else       { asm volatile("cp.async.wait_group 0;"); }
        __syncthreads();

        uint32_t st = sbase + (uint32_t)(c & 1) * G1_STAGE;
#pragma unroll
        for (int kk = 0; kk < 4; kk++) {
            uint32_t kb = (uint32_t)(kk * 32);   // 16 elems = 32 bytes
            uint32_t ah[4][4], al[4][4];
#pragma unroll
            for (int mi = 0; mi < 4; mi++) {
                uint32_t ad = st + G1_A_HI + (aRow + mi * 16) * G1_PITCHB + kb + aColB;
                LDSM4(ah[mi][0], ah[mi][1], ah[mi][2], ah[mi][3], ad);
                LDSM4(al[mi][0], al[mi][1], al[mi][2], al[mi][3], ad + (G1_A_LO - G1_A_HI));
            }
            uint32_t bh[4][2], bl[4][2];
#pragma unroll
            for (int nh = 0; nh < 2; nh++) {
                uint32_t bd = st + G1_B_HI + (bRow + nh * 16) * G1_PITCHB + kb + bColB;
                uint32_t t0, t1, t2, t3;
                LDSM4(t0, t1, t2, t3, bd);
                bh[nh * 2][0] = t0; bh[nh * 2][1] = t1;
                bh[nh * 2 + 1][0] = t2; bh[nh * 2 + 1][1] = t3;
                LDSM4(t0, t1, t2, t3, bd + (G1_B_LO - G1_B_HI));
                bl[nh * 2][0] = t0; bl[nh * 2][1] = t1;
                bl[nh * 2 + 1][0] = t2; bl[nh * 2 + 1][1] = t3;
            }
#pragma unroll
            for (int mi = 0; mi < 4; mi++) {
#pragma unroll
                for (int ni = 0; ni < 4; ni++) {
                    MMA16816(acc[mi][ni], ah[mi], bh[ni]);
                    MMA16816(acc[mi][ni], ah[mi], bl[ni]);
                    MMA16816(acc[mi][ni], al[mi], bh[ni]);
                }
            }
        }
        __syncthreads();
    }

    // epilogue: direct stores (each instr = 8 full 32B sectors)
#pragma unroll
    for (int mi = 0; mi < 4; mi++) {
#pragma unroll
        for (int ni = 0; ni < 4; ni++) {
            int grow = row0 + wm * 64 + mi * 16 + (lane >> 2);
            int gcol = col0 + wn * 32 + ni * 8 + (lane & 3) * 2;
            if (grow < M) {
                float2 v = make_float2(acc[mi][ni][0], acc[mi][ni][1]);
                *(float2*)(g_z1 + (size_t)grow * 256 + gcol) = v;
            }
            if (grow + 8 < M) {
                float2 v = make_float2(acc[mi][ni][2], acc[mi][ni][3]);
                *(float2*)(g_z1 + (size_t)(grow + 8) * 256 + gcol) = v;
            }
        }
    }
}

// ---------------- column stats for bn1 ----------------
__global__ void k_stats1(int M) {
    int c = threadIdx.x;   // 256
    int base = blockIdx.x * 512;
    float s = 0.f, s2 = 0.f;
    int end = M - base; if (end > 512) end = 512;
    for (int r = 0; r < end; r++) {
        float v = g_z1[(size_t)(base + r) * 256 + c];
        s += v; s2 += v * v;
    }
    atomicAdd(&g_stats1[c], s);
    atomicAdd(&g_stats1[256 + c], s2);
}

__global__ void k_bnp(const float* __restrict__ g, const float* __restrict__ b,
                      int C, float invM, int which) {
    int c = blockIdx.x * blockDim.x + threadIdx.x;
    if (c < C) {
        const float* st = which ? g_stats2 : g_stats1;
        float* sc = which ? g_bn2sc : g_bn1sc;
        float* sh = which ? g_bn2sh : g_bn1sh;
        float mu  = st[c] * invM;
        float var = st[C + c] * invM - mu * mu;
        float s = g[c] * rsqrtf(var + 0.001f);
        sc[c] = s;
        sh[c] = b[c] - mu * s;
    }
}

// ---------------- GEMM2: out = relu(bn1(z1)) @ W2(256x64), bn1 folded into A-load ----------------
__global__ void __launch_bounds__(256)
k_gemm2(const float* __restrict__ W, float* __restrict__ out, int M) {
    __shared__ __align__(16) float As[16][128];
    __shared__ __align__(16) float Bs[16][64];
    int tid = threadIdx.x;
    int row0 = blockIdx.x * 128;
    int tx = tid & 15, ty = tid >> 4;
    float acc[8][4] = {};
    for (int k0 = 0; k0 < 256; k0 += 16) {
#pragma unroll
        for (int q = 0; q < 2; q++) {
            int idx = tid * 2 + q;
            int ar = idx >> 2, kq = (idx & 3) * 4;
            float4 av = make_float4(0.f, 0.f, 0.f, 0.f);
            int gr = row0 + ar;
            if (gr < M) av = *(const float4*)(g_z1 + (size_t)gr * 256 + k0 + kq);
            float4 sc = *(const float4*)(g_bn1sc + k0 + kq);
            float4 sh = *(const float4*)(g_bn1sh + k0 + kq);
            av.x = fmaxf(av.x * sc.x + sh.x, 0.f);
            av.y = fmaxf(av.y * sc.y + sh.y, 0.f);
            av.z = fmaxf(av.z * sc.z + sh.z, 0.f);
            av.w = fmaxf(av.w * sc.w + sh.w, 0.f);
            As[kq + 0][ar] = av.x; As[kq + 1][ar] = av.y;
            As[kq + 2][ar] = av.z; As[kq + 3][ar] = av.w;
        }
        {
            int b_k = tid >> 4, b_c = (tid & 15) * 4;
            *(float4*)&Bs[b_k][b_c] = *(const float4*)(W + (size_t)(k0 + b_k) * 64 + b_c);
        }
        __syncthreads();
#pragma unroll
        for (int k = 0; k < 16; k++) {
            float ar8[8], br4[4];
            *(float4*)(ar8)     = *(float4*)&As[k][ty * 8];
            *(float4*)(ar8 + 4) = *(float4*)&As[k][ty * 8 + 4];
            *(float4*)(br4)     = *(float4*)&Bs[k][tx * 4];
#pragma unroll
            for (int i = 0; i < 8; i++)
#pragma unroll
                for (int jj = 0; jj < 4; jj++) acc[i][jj] += ar8[i] * br4[jj];
        }
        __syncthreads();
    }
#pragma unroll
    for (int i = 0; i < 8; i++) {
        int gr = row0 + ty * 8 + i;
        if (gr < M) *(float4*)(out + (size_t)gr * 64 + tx * 4) = *(float4*)&acc[i][0];
    }
}

// ---------------- column stats for bn2 ----------------
__global__ void k_stats2(const float* __restrict__ z2, int M) {
    int c = threadIdx.x & 63, ro = threadIdx.x >> 6;
    int base = blockIdx.x * 1024;
    float s = 0.f, s2 = 0.f;
    for (int r = ro; r < 1024; r += 4) {
        int j = base + r;
        if (j >= M) break;
        float v = z2[(size_t)j * 64 + c];
        s += v; s2 += v * v;
    }
    atomicAdd(&g_stats2[c], s);
    atomicAdd(&g_stats2[64 + c], s2);
}

__global__ void k_final(float* __restrict__ out, int n) {
    int i = blockIdx.x * blockDim.x + threadIdx.x;
    if (i < n) {
        int c = i & 63;
        out[i] = fmaxf(out[i] * g_bn2sc[c] + g_bn2sh[c], 0.f);
    }
}

// ---------------- launcher ----------------
extern "C" void kernel_launch(void* const* d_in, const int* in_sizes, int n_in,
                              void* d_out, int out_size) {
    const float* vf      = (const float*)d_in[0];
    const int*   coords  = (const int*)d_in[1];
    const int*   inv     = (const int*)d_in[3];
    const int*   cnt     = (const int*)d_in[4];
    const float* up_w1   = (const float*)d_in[5];
    const float* up_b1   = (const float*)d_in[6];
    const float* up_w2   = (const float*)d_in[7];
    const float* up_b2   = (const float*)d_in[8];
    const float* ca_w1   = (const float*)d_in[9];
    const float* ca_w2   = (const float*)d_in[10];
    const float* sa_conv = (const float*)d_in[11];
    const float* bs_w1   = (const float*)d_in[12];
    const float* bn1_g   = (const float*)d_in[13];
    const float* bn1_b   = (const float*)d_in[14];
    const float* bs_w2   = (const float*)d_in[15];
    const float* bn2_g   = (const float*)d_in[16];
    const float* bn2_b   = (const float*)d_in[17];

    int Nv = in_sizes[0] / 5;
    int U  = in_sizes[2];
    int M  = out_size / 64;
    if (M <= 0) return;

    int nwin = U * 8;
    k_init<<<(nwin + 255) / 256, 256>>>(nwin);
    k_scatter<<<(Nv + 255) / 256, 256>>>(coords, inv, Nv);

    int NB = (U + 1023) / 1024;
    k_count<<<NB, 256>>>(cnt, U);
    k_scan<<<1, 1>>>(NB);
    k_compact<<<NB, 256>>>(cnt, U);

    k_hempty<<<1, 64>>>(up_b1, up_w2, up_b2);
    k_prepw<<<512, 256>>>(bs_w1);
    k_rows<<<(M + 7) / 8, 256>>>(vf, up_w1, up_b1, up_w2, up_b2,
                                 ca_w1, ca_w2, sa_conv, M);

    // mma.sync GEMM1
    {
        int dynsmem = 2 * G1_STAGE;
        cudaFuncSetAttribute(k_gemm1_mma, cudaFuncAttributeMaxDynamicSharedMemorySize, dynsmem);
        dim3 g1((M + 127) / 128, 2);
        k_gemm1_mma<<<g1, 256, dynsmem>>>(M);
    }
    k_stats1<<<(M + 511) / 512, 256>>>(M);
    k_bnp<<<1, 256>>>(bn1_g, bn1_b, 256, 1.f / (float)M, 0);

    k_gemm2<<<(M + 127) / 128, 256>>>(bs_w2, (float*)d_out, M);
    k_stats2<<<(M + 1023) / 1024, 256>>>((const float*)d_out, M);
    k_bnp<<<1, 64>>>(bn2_g, bn2_b, 64, 1.f / (float)M, 1);
    k_final<<<(M * 64 + 255) / 256, 256>>>((float*)d_out, M * 64);
}

// round 6
// speedup vs baseline: 2.8837x; 2.1912x over previous
#include <cuda_runtime.h>
#include <cuda_bf16.h>
#include <math.h>
#include <stdint.h>

// ---------------- static scratch (allocation-free) ----------------
#define UMAX 200000
__device__ int   g_winner[UMAX * 8];
__device__ int   g_selrows[UMAX];
__device__ int   g_bsum[256];
__device__ __align__(16) __nv_bfloat16 g_flat_hi[(size_t)UMAX * 512];
__device__ __align__(16) __nv_bfloat16 g_flat_lo[(size_t)UMAX * 512];
__device__ __align__(16) __nv_bfloat16 g_wt_hi[256 * 512];
__device__ __align__(16) __nv_bfloat16 g_wt_lo[256 * 512];
__device__ __align__(16) float g_z1[(size_t)UMAX * 256];
__device__ __align__(16) float g_stats1[512];   // sum[256] | sumsq[256]
__device__ __align__(16) float g_stats2[128];   // sum[64]  | sumsq[64]
__device__ __align__(16) float g_bn1sc[256];
__device__ __align__(16) float g_bn1sh[256];
__device__ __align__(16) float g_bn2sc[64];
__device__ __align__(16) float g_bn2sh[64];

__device__ __forceinline__ uint32_t smem_u32(const void* p) {
    uint32_t a;
    asm("{ .reg .u64 t; cvta.to.shared.u64 t, %1; cvt.u32.u64 %0, t; }" : "=r"(a) : "l"(p));
    return a;
}

// ---------------- init ----------------
__global__ void k_init(int nwin) {
    int i = blockIdx.x * blockDim.x + threadIdx.x;
    if (i < nwin) g_winner[i] = -1;
    if (i < 512)  g_stats1[i] = 0.f;
    if (i < 128)  g_stats2[i] = 0.f;
}

// ---------------- scatter: last-write-wins via max voxel index ----------------
__global__ void k_scatter(const int* __restrict__ coords, const int* __restrict__ inv, int Nv) {
    int i = blockIdx.x * blockDim.x + threadIdx.x;
    if (i < Nv) {
        int z = coords[(size_t)i * 4 + 1];
        int u = inv[i];
        atomicMax(&g_winner[(size_t)u * 8 + z], i);
    }
}

// ---------------- ordered compaction of rows with cnt>=2 ----------------
__global__ void k_count(const int* __restrict__ cnt, int U) {
    __shared__ int s[256];
    int base = blockIdx.x * 1024;
    int c = 0;
    for (int t = threadIdx.x; t < 1024; t += 256) {
        int u = base + t;
        if (u < U && cnt[u] >= 2) c++;
    }
    s[threadIdx.x] = c;
    __syncthreads();
    for (int o = 128; o > 0; o >>= 1) {
        if (threadIdx.x < o) s[threadIdx.x] += s[threadIdx.x + o];
        __syncthreads();
    }
    if (threadIdx.x == 0) g_bsum[blockIdx.x] = s[0];
}

__global__ void k_scan(int nb) {
    int acc = 0;
    for (int b = 0; b < nb; b++) { int v = g_bsum[b]; g_bsum[b] = acc; acc += v; }
}

__global__ void k_compact(const int* __restrict__ cnt, int U) {
    __shared__ int s[256];
    int tid = threadIdx.x;
    int base = blockIdx.x * 1024 + tid * 4;
    int flags[4]; int c = 0;
    for (int q = 0; q < 4; q++) {
        int u = base + q;
        flags[q] = (u < U && cnt[u] >= 2) ? 1 : 0;
        c += flags[q];
    }
    s[tid] = c;
    __syncthreads();
    for (int o = 1; o < 256; o <<= 1) {
        int v = (tid >= o) ? s[tid - o] : 0;
        __syncthreads();
        s[tid] += v;
        __syncthreads();
    }
    int off = g_bsum[blockIdx.x] + s[tid] - c;
    for (int q = 0; q < 4; q++) {
        if (flags[q]) g_selrows[off++] = base + q;
    }
}

// ---------------- weight transpose + bf16 split: Wt[n][k] hi/lo ----------------
__global__ void k_prepw(const float* __restrict__ W) {
    int i = blockIdx.x * 256 + threadIdx.x;   // 131072 total
    int n = i >> 9, k = i & 511;
    float w = W[(size_t)k * 256 + n];
    __nv_bfloat16 hi = __float2bfloat16(w);
    float lo = w - __bfloat162float(hi);
    g_wt_hi[i] = hi;
    g_wt_lo[i] = __float2bfloat16(lo);
}

// ---------------- fused per-row (warp-per-row): slot MLP + CBAM + flatten ----------------
__global__ void __launch_bounds__(256)
k_rows2(const float* __restrict__ vf,
        const float* __restrict__ w1, const float* __restrict__ b1,
        const float* __restrict__ w2g, const float* __restrict__ b2,
        const float* __restrict__ caw1, const float* __restrict__ caw2,
        const float* __restrict__ saconv, int M)
{
    __shared__ float sw1[160], sb1[32], sb2[64];
    __shared__ float scw1[512], scw2[512], sconv[16];
    __shared__ float sfeatw[8][40];
    __shared__ __align__(16) float shidw[8][8][32];

    const unsigned FULL = 0xffffffffu;
    int tid  = threadIdx.x;
    int wid  = tid >> 5;
    int lane = tid & 31;

    for (int i = tid; i < 160; i += 256) sw1[i] = w1[i];
    if (tid < 32) sb1[tid] = b1[tid];
    if (tid < 64) sb2[tid] = b2[tid];
    for (int i = tid; i < 512; i += 256) scw1[i] = caw1[i];
    for (int i = tid; i < 512; i += 256) scw2[i] = caw2[i];
    if (tid < 14) sconv[tid] = saconv[tid];

    // per-lane register cache of two w2 columns
    float w2a[32], w2b[32];
#pragma unroll
    for (int k = 0; k < 32; k++) {
        w2a[k] = w2g[k * 64 + lane];
        w2b[k] = w2g[k * 64 + lane + 32];
    }
    __syncthreads();

    for (int r = 0; r < 8; r++) {
        int j = blockIdx.x * 64 + wid * 8 + r;
        if (j >= M) break;
        int u = g_selrows[j];
        int wv = (lane < 8) ? g_winner[(size_t)u * 8 + lane] : -1;

        // gather 40 features (8 bins x 5); shuffles executed by ALL lanes
#pragma unroll
        for (int q = 0; q < 2; q++) {
            int t = lane + q * 32;
            int valid = (t < 40);
            int zz = valid ? (t / 5) : 0;
            int f  = t - zz * 5;
            int w = __shfl_sync(FULL, wv, zz);
            if (valid) sfeatw[wid][t] = (w >= 0) ? vf[(size_t)w * 5 + f] : 0.f;
        }
        __syncwarp();

        // hidden layer: lane = hidden unit k, loop over bins
#pragma unroll
        for (int z = 0; z < 8; z++) {
            float a = sb1[lane];
#pragma unroll
            for (int f = 0; f < 5; f++) a += sfeatw[wid][z * 5 + f] * sw1[f * 32 + lane];
            shidw[wid][z][lane] = fmaxf(a, 0.f);
        }
        __syncwarp();

        // output layer: lane owns channels (lane, lane+32)
        float x0[8], x1[8];
#pragma unroll
        for (int z = 0; z < 8; z++) {
            float a0 = sb2[lane], a1 = sb2[lane + 32];
            const float* hz = &shidw[wid][z][0];
#pragma unroll
            for (int k4 = 0; k4 < 8; k4++) {
                float4 h = *(const float4*)(hz + k4 * 4);
                a0 += h.x * w2a[k4 * 4] + h.y * w2a[k4 * 4 + 1] + h.z * w2a[k4 * 4 + 2] + h.w * w2a[k4 * 4 + 3];
                a1 += h.x * w2b[k4 * 4] + h.y * w2b[k4 * 4 + 1] + h.z * w2b[k4 * 4 + 2] + h.w * w2b[k4 * 4 + 3];
            }
            x0[z] = a0; x1[z] = a1;
        }

        // channel stats (over bins) straight from registers
        float m0 = 0.f, m1 = 0.f, q0 = -3.4e38f, q1 = -3.4e38f;
#pragma unroll
        for (int z = 0; z < 8; z++) {
            m0 += x0[z]; m1 += x1[z];
            q0 = fmaxf(q0, x0[z]); q1 = fmaxf(q1, x1[z]);
        }
        m0 *= 0.125f; m1 *= 0.125f;

        // ca hidden: 8 units, warp-reduced over 64 channels (2 per lane)
        float s8[8];
#pragma unroll
        for (int r8 = 0; r8 < 8; r8++) {
            float pm = m0 * scw1[lane * 8 + r8] + m1 * scw1[(lane + 32) * 8 + r8];
            float px = q0 * scw1[lane * 8 + r8] + q1 * scw1[(lane + 32) * 8 + r8];
#pragma unroll
            for (int o = 16; o > 0; o >>= 1) {
                pm += __shfl_xor_sync(FULL, pm, o);
                px += __shfl_xor_sync(FULL, px, o);
            }
            s8[r8] = fmaxf(pm, 0.f) + fmaxf(px, 0.f);
        }

        // ca output + sigmoid, apply
        float a0 = 0.f, a1 = 0.f;
#pragma unroll
        for (int r8 = 0; r8 < 8; r8++) {
            a0 += s8[r8] * scw2[r8 * 64 + lane];
            a1 += s8[r8] * scw2[r8 * 64 + lane + 32];
        }
        float ca0 = 1.f / (1.f + expf(-a0));
        float ca1 = 1.f / (1.f + expf(-a1));
#pragma unroll
        for (int z = 0; z < 8; z++) { x0[z] *= ca0; x1[z] *= ca1; }

        // spatial stats per bin: mean/max over 64 channels
        float szm[8], szx[8];
#pragma unroll
        for (int z = 0; z < 8; z++) {
            float s = x0[z] + x1[z];
            float m = fmaxf(x0[z], x1[z]);
#pragma unroll
            for (int o = 16; o > 0; o >>= 1) {
                s += __shfl_xor_sync(FULL, s, o);
                m = fmaxf(m, __shfl_xor_sync(FULL, m, o));
            }
            szm[z] = s * (1.f / 64.f);
            szx[z] = m;
        }

        // spatial conv (7-tap, 2-in-ch) + sigmoid; lane<8 computes, broadcast
        float sav = 0.f;
        if (lane < 8) {
            float acc = 0.f;
#pragma unroll
            for (int t = 0; t < 7; t++) {
                int p = lane + t - 3;
                if (p >= 0 && p < 8) acc += szm[p] * sconv[t] + szx[p] * sconv[7 + t];
            }
            sav = 1.f / (1.f + expf(-acc));
        }
        float sa[8];
#pragma unroll
        for (int z = 0; z < 8; z++) sa[z] = __shfl_sync(FULL, sav, z);

        // write flat: out[c*8+z] as bf16 hi/lo, one 16B store per half
        size_t base = (size_t)j * 512;
        uint32_t ph[4], pl[4];
#pragma unroll
        for (int z2 = 0; z2 < 4; z2++) {
            float v0 = x0[2 * z2] * sa[2 * z2];
            float v1 = x0[2 * z2 + 1] * sa[2 * z2 + 1];
            __nv_bfloat162 h2 = __floats2bfloat162_rn(v0, v1);
            float l0 = v0 - __bfloat162float(__low2bfloat16(h2));
            float l1 = v1 - __bfloat162float(__high2bfloat16(h2));
            __nv_bfloat162 l2 = __floats2bfloat162_rn(l0, l1);
            ph[z2] = *(uint32_t*)&h2;
            pl[z2] = *(uint32_t*)&l2;
        }
        *(uint4*)&g_flat_hi[base + lane * 8] = *(uint4*)ph;
        *(uint4*)&g_flat_lo[base + lane * 8] = *(uint4*)pl;
#pragma unroll
        for (int z2 = 0; z2 < 4; z2++) {
            float v0 = x1[2 * z2] * sa[2 * z2];
            float v1 = x1[2 * z2 + 1] * sa[2 * z2 + 1];
            __nv_bfloat162 h2 = __floats2bfloat162_rn(v0, v1);
            float l0 = v0 - __bfloat162float(__low2bfloat16(h2));
            float l1 = v1 - __bfloat162float(__high2bfloat16(h2));
            __nv_bfloat162 l2 = __floats2bfloat162_rn(l0, l1);
            ph[z2] = *(uint32_t*)&h2;
            pl[z2] = *(uint32_t*)&l2;
        }
        *(uint4*)&g_flat_hi[base + (lane + 32) * 8] = *(uint4*)ph;
        *(uint4*)&g_flat_lo[base + (lane + 32) * 8] = *(uint4*)pl;
        __syncwarp();
    }
}

// ---------------- GEMM1 (mma.sync bf16 hi/lo split) + fused bn1 stats ----------------
#define G1_PITCHB  144                 // bytes per smem row (72 bf16)
#define G1_A_HI    0
#define G1_A_LO    18432
#define G1_B_HI    36864
#define G1_B_LO    55296
#define G1_STAGE   73728

#define LDSM4(R0, R1, R2, R3, ADDR) \
    asm volatile("ldmatrix.sync.aligned.m8n8.x4.shared.b16 {%0,%1,%2,%3}, [%4];" \
                 : "=r"(R0), "=r"(R1), "=r"(R2), "=r"(R3) : "r"(ADDR))

#define MMA16816(D, A, B) \
    asm volatile("mma.sync.aligned.m16n8k16.row.col.f32.bf16.bf16.f32 " \
                 "{%0,%1,%2,%3}, {%4,%5,%6,%7}, {%8,%9}, {%0,%1,%2,%3};" \
                 : "+f"((D)[0]), "+f"((D)[1]), "+f"((D)[2]), "+f"((D)[3]) \
                 : "r"((A)[0]), "r"((A)[1]), "r"((A)[2]), "r"((A)[3]), \
                   "r"((B)[0]), "r"((B)[1]))

__device__ __forceinline__ void cp16(uint32_t saddr, const void* gaddr, uint32_t sz) {
    asm volatile("cp.async.cg.shared.global [%0], [%1], 16, %2;"
                 :: "r"(saddr), "l"(gaddr), "r"(sz));
}

__global__ void __launch_bounds__(256, 1)
k_gemm1_mma(int M) {
    extern __shared__ __align__(16) char dsm[];
    uint32_t sbase = smem_u32(dsm);
    const unsigned FULL = 0xffffffffu;

    int tid  = threadIdx.x;
    int lane = tid & 31;
    int wid  = tid >> 5;
    int wm = wid & 1;        // 2 m-warps (64 rows each)
    int wn = wid >> 1;       // 4 n-warps (32 cols each)
    int row0 = blockIdx.x * 128;
    int col0 = blockIdx.y * 128;

    int li_r  = tid >> 3;
    int li_c8 = tid & 7;

    float acc[4][4][4] = {};

    auto load_chunk = [&](int c) {
        uint32_t st = sbase + (uint32_t)(c & 1) * G1_STAGE;
#pragma unroll
        for (int it = 0; it < 4; it++) {
            int r = li_r + it * 32;
            int gr = row0 + r;
            uint32_t soff = (uint32_t)(r * G1_PITCHB + li_c8 * 16);
            size_t goff = (size_t)gr * 512 + c * 64 + li_c8 * 8;
            uint32_t sz = (gr < M) ? 16u : 0u;
            cp16(st + G1_A_HI + soff, g_flat_hi + goff, sz);
            cp16(st + G1_A_LO + soff, g_flat_lo + goff, sz);
            int n = col0 + r;
            size_t boff = (size_t)n * 512 + c * 64 + li_c8 * 8;
            cp16(st + G1_B_HI + soff, g_wt_hi + boff, 16u);
            cp16(st + G1_B_LO + soff, g_wt_lo + boff, 16u);
        }
        asm volatile("cp.async.commit_group;");
    };

    load_chunk(0);

    uint32_t aRow  = (uint32_t)(wm * 64 + (lane & 15));
    uint32_t aColB = (uint32_t)((lane >> 4) * 16);
    uint32_t bRow  = (uint32_t)(wn * 32 + ((lane >> 4) & 1) * 8 + (lane & 7));
    uint32_t bColB = (uint32_t)(((lane >> 3) & 1) * 16);

    for (int c = 0; c < 8; c++) {
        if (c < 7) load_chunk(c + 1);
        if (c < 7) { asm volatile("cp.async.wait_group 1;"); }
        else       { asm volatile("cp.async.wait_group 0;"); }
        __syncthreads();

        uint32_t st = sbase + (uint32_t)(c & 1) * G1_STAGE;
#pragma unroll
        for (int kk = 0; kk < 4; kk++) {
            uint32_t kb = (uint32_t)(kk * 32);
            uint32_t ah[4][4], al[4][4];
#pragma unroll
            for (int mi = 0; mi < 4; mi++) {
                uint32_t ad = st + G1_A_HI + (aRow + mi * 16) * G1_PITCHB + kb + aColB;
                LDSM4(ah[mi][0], ah[mi][1], ah[mi][2], ah[mi][3], ad);
                LDSM4(al[mi][0], al[mi][1], al[mi][2], al[mi][3], ad + (G1_A_LO - G1_A_HI));
            }
            uint32_t bh[4][2], bl[4][2];
#pragma unroll
            for (int nh = 0; nh < 2; nh++) {
                uint32_t bd = st + G1_B_HI + (bRow + nh * 16) * G1_PITCHB + kb + bColB;
                uint32_t t0, t1, t2, t3;
                LDSM4(t0, t1, t2, t3, bd);
                bh[nh * 2][0] = t0; bh[nh * 2][1] = t1;
                bh[nh * 2 + 1][0] = t2; bh[nh * 2 + 1][1] = t3;
                LDSM4(t0, t1, t2, t3, bd + (G1_B_LO - G1_B_HI));
                bl[nh * 2][0] = t0; bl[nh * 2][1] = t1;
                bl[nh * 2 + 1][0] = t2; bl[nh * 2 + 1][1] = t3;
            }
#pragma unroll
            for (int mi = 0; mi < 4; mi++) {
#pragma unroll
                for (int ni = 0; ni < 4; ni++) {
                    MMA16816(acc[mi][ni], ah[mi], bh[ni]);
                    MMA16816(acc[mi][ni], ah[mi], bl[ni]);
                    MMA16816(acc[mi][ni], al[mi], bh[ni]);
                }
            }
        }
        __syncthreads();
    }

    // stores
#pragma unroll
    for (int mi = 0; mi < 4; mi++) {
#pragma unroll
        for (int ni = 0; ni < 4; ni++) {
            int grow = row0 + wm * 64 + mi * 16 + (lane >> 2);
            int gcol = col0 + wn * 32 + ni * 8 + (lane & 3) * 2;
            if (grow < M) {
                float2 v = make_float2(acc[mi][ni][0], acc[mi][ni][1]);
                *(float2*)(g_z1 + (size_t)grow * 256 + gcol) = v;
            }
            if (grow + 8 < M) {
                float2 v = make_float2(acc[mi][ni][2], acc[mi][ni][3]);
                *(float2*)(g_z1 + (size_t)(grow + 8) * 256 + gcol) = v;
            }
        }
    }

    // fused bn1 column stats (OOB rows are exact zeros via zfill)
#pragma unroll
    for (int ni = 0; ni < 4; ni++) {
#pragma unroll
        for (int jj = 0; jj < 2; jj++) {
            float s = 0.f, s2 = 0.f;
#pragma unroll
            for (int mi = 0; mi < 4; mi++) {
                float v0 = acc[mi][ni][jj], v1 = acc[mi][ni][jj + 2];
                s += v0 + v1; s2 += v0 * v0 + v1 * v1;
            }
#pragma unroll
            for (int o = 4; o <= 16; o <<= 1) {
                s  += __shfl_xor_sync(FULL, s, o);
                s2 += __shfl_xor_sync(FULL, s2, o);
            }
            if ((lane >> 2) == 0) {
                int col = col0 + wn * 32 + ni * 8 + (lane & 3) * 2 + jj;
                atomicAdd(&g_stats1[col], s);
                atomicAdd(&g_stats1[256 + col], s2);
            }
        }
    }
}

__global__ void k_bnp(const float* __restrict__ g, const float* __restrict__ b,
                      int C, float invM, int which) {
    int c = blockIdx.x * blockDim.x + threadIdx.x;
    if (c < C) {
        const float* st = which ? g_stats2 : g_stats1;
        float* sc = which ? g_bn2sc : g_bn1sc;
        float* sh = which ? g_bn2sh : g_bn1sh;
        float mu  = st[c] * invM;
        float var = st[C + c] * invM - mu * mu;
        float s = g[c] * rsqrtf(var + 0.001f);
        sc[c] = s;
        sh[c] = b[c] - mu * s;
    }
}

// ---------------- GEMM2: out = relu(bn1(z1)) @ W2(256x64) + fused bn2 stats ----------------
__global__ void __launch_bounds__(256)
k_gemm2(const float* __restrict__ W, float* __restrict__ out, int M) {
    __shared__ __align__(16) float As[16][128];
    __shared__ __align__(16) float Bs[16][64];
    __shared__ float ss[128];
    int tid = threadIdx.x;
    int row0 = blockIdx.x * 128;
    int tx = tid & 15, ty = tid >> 4;
    float acc[8][4] = {};
    if (tid < 128) ss[tid] = 0.f;
    for (int k0 = 0; k0 < 256; k0 += 16) {
#pragma unroll
        for (int q = 0; q < 2; q++) {
            int idx = tid * 2 + q;
            int ar = idx >> 2, kq = (idx & 3) * 4;
            float4 av = make_float4(0.f, 0.f, 0.f, 0.f);
            int gr = row0 + ar;
            if (gr < M) {
                av = *(const float4*)(g_z1 + (size_t)gr * 256 + k0 + kq);
                float4 sc = *(const float4*)(g_bn1sc + k0 + kq);
                float4 sh = *(const float4*)(g_bn1sh + k0 + kq);
                av.x = fmaxf(av.x * sc.x + sh.x, 0.f);
                av.y = fmaxf(av.y * sc.y + sh.y, 0.f);
                av.z = fmaxf(av.z * sc.z + sh.z, 0.f);
                av.w = fmaxf(av.w * sc.w + sh.w, 0.f);
            }
            As[kq + 0][ar] = av.x; As[kq + 1][ar] = av.y;
            As[kq + 2][ar] = av.z; As[kq + 3][ar] = av.w;
        }
        {
            int b_k = tid >> 4, b_c = (tid & 15) * 4;
            *(float4*)&Bs[b_k][b_c] = *(const float4*)(W + (size_t)(k0 + b_k) * 64 + b_c);
        }
        __syncthreads();
#pragma unroll
        for (int k = 0; k < 16; k++) {
            float ar8[8], br4[4];
            *(float4*)(ar8)     = *(float4*)&As[k][ty * 8];
            *(float4*)(ar8 + 4) = *(float4*)&As[k][ty * 8 + 4];
            *(float4*)(br4)     = *(float4*)&Bs[k][tx * 4];
#pragma unroll
            for (int i = 0; i < 8; i++)
#pragma unroll
                for (int jj = 0; jj < 4; jj++) acc[i][jj] += ar8[i] * br4[jj];
        }
        __syncthreads();
    }
#pragma unroll
    for (int i = 0; i < 8; i++) {
        int gr = row0 + ty * 8 + i;
        if (gr < M) *(float4*)(out + (size_t)gr * 64 + tx * 4) = *(float4*)&acc[i][0];
    }
    // fused bn2 stats: OOB rows contribute zeros (A rows were zeroed)
#pragma unroll
    for (int q = 0; q < 4; q++) {
        float s = 0.f, s2 = 0.f;
#pragma unroll
        for (int i = 0; i < 8; i++) { float v = acc[i][q]; s += v; s2 += v * v; }
        atomicAdd(&ss[tx * 4 + q], s);
        atomicAdd(&ss[64 + tx * 4 + q], s2);
    }
    __syncthreads();
    if (tid < 64) {
        atomicAdd(&g_stats2[tid], ss[tid]);
        atomicAdd(&g_stats2[64 + tid], ss[64 + tid]);
    }
}

__global__ void k_final(float* __restrict__ out, int n) {
    int i = blockIdx.x * blockDim.x + threadIdx.x;
    if (i < n) {
        int c = i & 63;
        out[i] = fmaxf(out[i] * g_bn2sc[c] + g_bn2sh[c], 0.f);
    }
}

// ---------------- launcher ----------------
extern "C" void kernel_launch(void* const* d_in, const int* in_sizes, int n_in,
                              void* d_out, int out_size) {
    const float* vf      = (const float*)d_in[0];
    const int*   coords  = (const int*)d_in[1];
    const int*   inv     = (const int*)d_in[3];
    const int*   cnt     = (const int*)d_in[4];
    const float* up_w1   = (const float*)d_in[5];
    const float* up_b1   = (const float*)d_in[6];
    const float* up_w2   = (const float*)d_in[7];
    const float* up_b2   = (const float*)d_in[8];
    const float* ca_w1   = (const float*)d_in[9];
    const float* ca_w2   = (const float*)d_in[10];
    const float* sa_conv = (const float*)d_in[11];
    const float* bs_w1   = (const float*)d_in[12];
    const float* bn1_g   = (const float*)d_in[13];
    const float* bn1_b   = (const float*)d_in[14];
    const float* bs_w2   = (const float*)d_in[15];
    const float* bn2_g   = (const float*)d_in[16];
    const float* bn2_b   = (const float*)d_in[17];

    int Nv = in_sizes[0] / 5;
    int U  = in_sizes[2];
    int M  = out_size / 64;
    if (M <= 0) return;

    int nwin = U * 8;
    k_init<<<(nwin + 255) / 256, 256>>>(nwin);
    k_scatter<<<(Nv + 255) / 256, 256>>>(coords, inv, Nv);

    int NB = (U + 1023) / 1024;
    k_count<<<NB, 256>>>(cnt, U);
    k_scan<<<1, 1>>>(NB);
    k_compact<<<NB, 256>>>(cnt, U);

    k_prepw<<<512, 256>>>(bs_w1);
    k_rows2<<<(M + 63) / 64, 256>>>(vf, up_w1, up_b1, up_w2, up_b2,
                                    ca_w1, ca_w2, sa_conv, M);

    {
        int dynsmem = 2 * G1_STAGE;
        cudaFuncSetAttribute(k_gemm1_mma, cudaFuncAttributeMaxDynamicSharedMemorySize, dynsmem);
        dim3 g1((M + 127) / 128, 2);
        k_gemm1_mma<<<g1, 256, dynsmem>>>(M);
    }
    k_bnp<<<1, 256>>>(bn1_g, bn1_b, 256, 1.f / (float)M, 0);

    k_gemm2<<<(M + 127) / 128, 256>>>(bs_w2, (float*)d_out, M);
    k_bnp<<<1, 64>>>(bn2_g, bn2_b, 64, 1.f / (float)M, 1);
    k_final<<<(M * 64 + 255) / 256, 256>>>((float*)d_out, M * 64);
}

// round 7
// speedup vs baseline: 2.9316x; 1.0166x over previous
#include <cuda_runtime.h>
#include <cuda_bf16.h>
#include <math.h>
#include <stdint.h>

// ---------------- static scratch (allocation-free) ----------------
#define UMAX 200000
__device__ int   g_winner[UMAX * 8];
__device__ int   g_selrows[UMAX];
__device__ int   g_bsum[256];
__device__ __align__(16) __nv_bfloat16 g_flat_hi[(size_t)UMAX * 512];
__device__ __align__(16) __nv_bfloat16 g_flat_lo[(size_t)UMAX * 512];
__device__ __align__(16) __nv_bfloat16 g_wt_hi[256 * 512];
__device__ __align__(16) __nv_bfloat16 g_wt_lo[256 * 512];
__device__ __align__(16) __nv_bfloat16 g_w2t_hi[64 * 256];
__device__ __align__(16) __nv_bfloat16 g_w2t_lo[64 * 256];
__device__ __align__(16) float g_z1[(size_t)UMAX * 256];
__device__ __align__(16) float g_stats1[512];   // sum[256] | sumsq[256]
__device__ __align__(16) float g_stats2[128];   // sum[64]  | sumsq[64]
__device__ __align__(16) float g_bn1sc[256];
__device__ __align__(16) float g_bn1sh[256];
__device__ __align__(16) float g_bn2sc[64];
__device__ __align__(16) float g_bn2sh[64];

__device__ __forceinline__ uint32_t smem_u32(const void* p) {
    uint32_t a;
    asm("{ .reg .u64 t; cvta.to.shared.u64 t, %1; cvt.u32.u64 %0, t; }" : "=r"(a) : "l"(p));
    return a;
}

// ---------------- init ----------------
__global__ void k_init(int nwin) {
    int i = blockIdx.x * blockDim.x + threadIdx.x;
    if (i < nwin) g_winner[i] = -1;
    if (i < 512)  g_stats1[i] = 0.f;
    if (i < 128)  g_stats2[i] = 0.f;
}

// ---------------- scatter: last-write-wins via max voxel index ----------------
__global__ void k_scatter(const int* __restrict__ coords, const int* __restrict__ inv, int Nv) {
    int i = blockIdx.x * blockDim.x + threadIdx.x;
    if (i < Nv) {
        int z = coords[(size_t)i * 4 + 1];
        int u = inv[i];
        atomicMax(&g_winner[(size_t)u * 8 + z], i);
    }
}

// ---------------- ordered compaction of rows with cnt>=2 ----------------
__global__ void k_count(const int* __restrict__ cnt, int U) {
    __shared__ int s[256];
    int base = blockIdx.x * 1024;
    int c = 0;
    for (int t = threadIdx.x; t < 1024; t += 256) {
        int u = base + t;
        if (u < U && cnt[u] >= 2) c++;
    }
    s[threadIdx.x] = c;
    __syncthreads();
    for (int o = 128; o > 0; o >>= 1) {
        if (threadIdx.x < o) s[threadIdx.x] += s[threadIdx.x + o];
        __syncthreads();
    }
    if (threadIdx.x == 0) g_bsum[blockIdx.x] = s[0];
}

__global__ void k_scan2(int nb) {
    __shared__ int s[256];
    int t = threadIdx.x;
    int v = (t < nb) ? g_bsum[t] : 0;
    s[t] = v;
    __syncthreads();
    for (int o = 1; o < 256; o <<= 1) {
        int u = (t >= o) ? s[t - o] : 0;
        __syncthreads();
        s[t] += u;
        __syncthreads();
    }
    if (t < nb) g_bsum[t] = s[t] - v;   // exclusive
}

__global__ void k_compact(const int* __restrict__ cnt, int U) {
    __shared__ int s[256];
    int tid = threadIdx.x;
    int base = blockIdx.x * 1024 + tid * 4;
    int flags[4]; int c = 0;
    for (int q = 0; q < 4; q++) {
        int u = base + q;
        flags[q] = (u < U && cnt[u] >= 2) ? 1 : 0;
        c += flags[q];
    }
    s[tid] = c;
    __syncthreads();
    for (int o = 1; o < 256; o <<= 1) {
        int v = (tid >= o) ? s[tid - o] : 0;
        __syncthreads();
        s[tid] += v;
        __syncthreads();
    }
    int off = g_bsum[blockIdx.x] + s[tid] - c;
    for (int q = 0; q < 4; q++) {
        if (flags[q]) g_selrows[off++] = base + q;
    }
}

// ---------------- weight transpose + bf16 split ----------------
__global__ void k_prepw(const float* __restrict__ W) {
    int i = blockIdx.x * 256 + threadIdx.x;   // 131072 total
    int n = i >> 9, k = i & 511;
    float w = W[(size_t)k * 256 + n];
    __nv_bfloat16 hi = __float2bfloat16(w);
    float lo = w - __bfloat162float(hi);
    g_wt_hi[i] = hi;
    g_wt_lo[i] = __float2bfloat16(lo);
}

__global__ void k_prepw2(const float* __restrict__ W) {
    int i = blockIdx.x * 256 + threadIdx.x;   // 16384 total
    int n = i >> 8, k = i & 255;
    float w = W[(size_t)k * 64 + n];
    __nv_bfloat16 hi = __float2bfloat16(w);
    float lo = w - __bfloat162float(hi);
    g_w2t_hi[i] = hi;
    g_w2t_lo[i] = __float2bfloat16(lo);
}

// ---------------- fused per-row (warp-per-row): slot MLP + CBAM + flatten ----------------
__global__ void __launch_bounds__(256)
k_rows2(const float* __restrict__ vf,
        const float* __restrict__ w1, const float* __restrict__ b1,
        const float* __restrict__ w2g, const float* __restrict__ b2,
        const float* __restrict__ caw1, const float* __restrict__ caw2,
        const float* __restrict__ saconv, int M)
{
    __shared__ float sw1[160], sb1[32], sb2[64];
    __shared__ float scw1[512], scw2[512], sconv[16];
    __shared__ float sfeatw[8][40];
    __shared__ __align__(16) float shidw[8][8][32];

    const unsigned FULL = 0xffffffffu;
    int tid  = threadIdx.x;
    int wid  = tid >> 5;
    int lane = tid & 31;

    for (int i = tid; i < 160; i += 256) sw1[i] = w1[i];
    if (tid < 32) sb1[tid] = b1[tid];
    if (tid < 64) sb2[tid] = b2[tid];
    for (int i = tid; i < 512; i += 256) scw1[i] = caw1[i];
    for (int i = tid; i < 512; i += 256) scw2[i] = caw2[i];
    if (tid < 14) sconv[tid] = saconv[tid];

    float w2a[32], w2b[32];
#pragma unroll
    for (int k = 0; k < 32; k++) {
        w2a[k] = w2g[k * 64 + lane];
        w2b[k] = w2g[k * 64 + lane + 32];
    }
    __syncthreads();

    for (int r = 0; r < 8; r++) {
        int j = blockIdx.x * 64 + wid * 8 + r;
        if (j >= M) break;
        int u = g_selrows[j];
        int wv = (lane < 8) ? g_winner[(size_t)u * 8 + lane] : -1;

#pragma unroll
        for (int q = 0; q < 2; q++) {
            int t = lane + q * 32;
            int valid = (t < 40);
            int zz = valid ? (t / 5) : 0;
            int f  = t - zz * 5;
            int w = __shfl_sync(FULL, wv, zz);
            if (valid) sfeatw[wid][t] = (w >= 0) ? vf[(size_t)w * 5 + f] : 0.f;
        }
        __syncwarp();

#pragma unroll
        for (int z = 0; z < 8; z++) {
            float a = sb1[lane];
#pragma unroll
            for (int f = 0; f < 5; f++) a += sfeatw[wid][z * 5 + f] * sw1[f * 32 + lane];
            shidw[wid][z][lane] = fmaxf(a, 0.f);
        }
        __syncwarp();

        float x0[8], x1[8];
#pragma unroll
        for (int z = 0; z < 8; z++) {
            float a0 = sb2[lane], a1 = sb2[lane + 32];
            const float* hz = &shidw[wid][z][0];
#pragma unroll
            for (int k4 = 0; k4 < 8; k4++) {
                float4 h = *(const float4*)(hz + k4 * 4);
                a0 += h.x * w2a[k4 * 4] + h.y * w2a[k4 * 4 + 1] + h.z * w2a[k4 * 4 + 2] + h.w * w2a[k4 * 4 + 3];
                a1 += h.x * w2b[k4 * 4] + h.y * w2b[k4 * 4 + 1] + h.z * w2b[k4 * 4 + 2] + h.w * w2b[k4 * 4 + 3];
            }
            x0[z] = a0; x1[z] = a1;
        }

        float m0 = 0.f, m1 = 0.f, q0 = -3.4e38f, q1 = -3.4e38f;
#pragma unroll
        for (int z = 0; z < 8; z++) {
            m0 += x0[z]; m1 += x1[z];
            q0 = fmaxf(q0, x0[z]); q1 = fmaxf(q1, x1[z]);
        }
        m0 *= 0.125f; m1 *= 0.125f;

        float s8[8];
#pragma unroll
        for (int r8 = 0; r8 < 8; r8++) {
            float pm = m0 * scw1[lane * 8 + r8] + m1 * scw1[(lane + 32) * 8 + r8];
            float px = q0 * scw1[lane * 8 + r8] + q1 * scw1[(lane + 32) * 8 + r8];
#pragma unroll
            for (int o = 16; o > 0; o >>= 1) {
                pm += __shfl_xor_sync(FULL, pm, o);
                px += __shfl_xor_sync(FULL, px, o);
            }
            s8[r8] = fmaxf(pm, 0.f) + fmaxf(px, 0.f);
        }

        float a0 = 0.f, a1 = 0.f;
#pragma unroll
        for (int r8 = 0; r8 < 8; r8++) {
            a0 += s8[r8] * scw2[r8 * 64 + lane];
            a1 += s8[r8] * scw2[r8 * 64 + lane + 32];
        }
        float ca0 = 1.f / (1.f + expf(-a0));
        float ca1 = 1.f / (1.f + expf(-a1));
#pragma unroll
        for (int z = 0; z < 8; z++) { x0[z] *= ca0; x1[z] *= ca1; }

        float szm[8], szx[8];
#pragma unroll
        for (int z = 0; z < 8; z++) {
            float s = x0[z] + x1[z];
            float m = fmaxf(x0[z], x1[z]);
#pragma unroll
            for (int o = 16; o > 0; o >>= 1) {
                s += __shfl_xor_sync(FULL, s, o);
                m = fmaxf(m, __shfl_xor_sync(FULL, m, o));
            }
            szm[z] = s * (1.f / 64.f);
            szx[z] = m;
        }

        float sav = 0.f;
        if (lane < 8) {
            float acc = 0.f;
#pragma unroll
            for (int t = 0; t < 7; t++) {
                int p = lane + t - 3;
                if (p >= 0 && p < 8) acc += szm[p] * sconv[t] + szx[p] * sconv[7 + t];
            }
            sav = 1.f / (1.f + expf(-acc));
        }
        float sa[8];
#pragma unroll
        for (int z = 0; z < 8; z++) sa[z] = __shfl_sync(FULL, sav, z);

        size_t base = (size_t)j * 512;
        uint32_t ph[4], pl[4];
#pragma unroll
        for (int z2 = 0; z2 < 4; z2++) {
            float v0 = x0[2 * z2] * sa[2 * z2];
            float v1 = x0[2 * z2 + 1] * sa[2 * z2 + 1];
            __nv_bfloat162 h2 = __floats2bfloat162_rn(v0, v1);
            float l0 = v0 - __bfloat162float(__low2bfloat16(h2));
            float l1 = v1 - __bfloat162float(__high2bfloat16(h2));
            __nv_bfloat162 l2 = __floats2bfloat162_rn(l0, l1);
            ph[z2] = *(uint32_t*)&h2;
            pl[z2] = *(uint32_t*)&l2;
        }
        *(uint4*)&g_flat_hi[base + lane * 8] = *(uint4*)ph;
        *(uint4*)&g_flat_lo[base + lane * 8] = *(uint4*)pl;
#pragma unroll
        for (int z2 = 0; z2 < 4; z2++) {
            float v0 = x1[2 * z2] * sa[2 * z2];
            float v1 = x1[2 * z2 + 1] * sa[2 * z2 + 1];
            __nv_bfloat162 h2 = __floats2bfloat162_rn(v0, v1);
            float l0 = v0 - __bfloat162float(__low2bfloat16(h2));
            float l1 = v1 - __bfloat162float(__high2bfloat16(h2));
            __nv_bfloat162 l2 = __floats2bfloat162_rn(l0, l1);
            ph[z2] = *(uint32_t*)&h2;
            pl[z2] = *(uint32_t*)&l2;
        }
        *(uint4*)&g_flat_hi[base + (lane + 32) * 8] = *(uint4*)ph;
        *(uint4*)&g_flat_lo[base + (lane + 32) * 8] = *(uint4*)pl;
        __syncwarp();
    }
}

// ---------------- common mma macros ----------------
#define LDSM4(R0, R1, R2, R3, ADDR) \
    asm volatile("ldmatrix.sync.aligned.m8n8.x4.shared.b16 {%0,%1,%2,%3}, [%4];" \
                 : "=r"(R0), "=r"(R1), "=r"(R2), "=r"(R3) : "r"(ADDR))

#define MMA16816(D, A, B) \
    asm volatile("mma.sync.aligned.m16n8k16.row.col.f32.bf16.bf16.f32 " \
                 "{%0,%1,%2,%3}, {%4,%5,%6,%7}, {%8,%9}, {%0,%1,%2,%3};" \
                 : "+f"((D)[0]), "+f"((D)[1]), "+f"((D)[2]), "+f"((D)[3]) \
                 : "r"((A)[0]), "r"((A)[1]), "r"((A)[2]), "r"((A)[3]), \
                   "r"((B)[0]), "r"((B)[1]))

__device__ __forceinline__ void cp16(uint32_t saddr, const void* gaddr, uint32_t sz) {
    asm volatile("cp.async.cg.shared.global [%0], [%1], 16, %2;"
                 :: "r"(saddr), "l"(gaddr), "r"(sz));
}

// ---------------- GEMM1 (mma.sync bf16 hi/lo split) + fused bn1 stats ----------------
#define G1_PITCHB  144
#define G1_A_HI    0
#define G1_A_LO    18432
#define G1_B_HI    36864
#define G1_B_LO    55296
#define G1_STAGE   73728

__global__ void __launch_bounds__(256, 1)
k_gemm1_mma(int M) {
    extern __shared__ __align__(16) char dsm[];
    uint32_t sbase = smem_u32(dsm);
    const unsigned FULL = 0xffffffffu;

    int tid  = threadIdx.x;
    int lane = tid & 31;
    int wid  = tid >> 5;
    int wm = wid & 1;
    int wn = wid >> 1;
    int row0 = blockIdx.x * 128;
    int col0 = blockIdx.y * 128;

    int li_r  = tid >> 3;
    int li_c8 = tid & 7;

    float acc[4][4][4] = {};

    auto load_chunk = [&](int c) {
        uint32_t st = sbase + (uint32_t)(c & 1) * G1_STAGE;
#pragma unroll
        for (int it = 0; it < 4; it++) {
            int r = li_r + it * 32;
            int gr = row0 + r;
            uint32_t soff = (uint32_t)(r * G1_PITCHB + li_c8 * 16);
            size_t goff = (size_t)gr * 512 + c * 64 + li_c8 * 8;
            uint32_t sz = (gr < M) ? 16u : 0u;
            cp16(st + G1_A_HI + soff, g_flat_hi + goff, sz);
            cp16(st + G1_A_LO + soff, g_flat_lo + goff, sz);
            int n = col0 + r;
            size_t boff = (size_t)n * 512 + c * 64 + li_c8 * 8;
            cp16(st + G1_B_HI + soff, g_wt_hi + boff, 16u);
            cp16(st + G1_B_LO + soff, g_wt_lo + boff, 16u);
        }
        asm volatile("cp.async.commit_group;");
    };

    load_chunk(0);

    uint32_t aRow  = (uint32_t)(wm * 64 + (lane & 15));
    uint32_t aColB = (uint32_t)((lane >> 4) * 16);
    uint32_t bRow  = (uint32_t)(wn * 32 + ((lane >> 4) & 1) * 8 + (lane & 7));
    uint32_t bColB = (uint32_t)(((lane >> 3) & 1) * 16);

    for (int c = 0; c < 8; c++) {
        if (c < 7) load_chunk(c + 1);
        if (c < 7) { asm volatile("cp.async.wait_group 1;"); }
        else       { asm volatile("cp.async.wait_group 0;"); }
        __syncthreads();

        uint32_t st = sbase + (uint32_t)(c & 1) * G1_STAGE;
#pragma unroll
        for (int kk = 0; kk < 4; kk++) {
            uint32_t kb = (uint32_t)(kk * 32);
            uint32_t ah[4][4], al[4][4];
#pragma unroll
            for (int mi = 0; mi < 4; mi++) {
                uint32_t ad = st + G1_A_HI + (aRow + mi * 16) * G1_PITCHB + kb + aColB;
                LDSM4(ah[mi][0], ah[mi][1], ah[mi][2], ah[mi][3], ad);
                LDSM4(al[mi][0], al[mi][1], al[mi][2], al[mi][3], ad + (G1_A_LO - G1_A_HI));
            }
            uint32_t bh[4][2], bl[4][2];
#pragma unroll
            for (int nh = 0; nh < 2; nh++) {
                uint32_t bd = st + G1_B_HI + (bRow + nh * 16) * G1_PITCHB + kb + bColB;
                uint32_t t0, t1, t2, t3;
                LDSM4(t0, t1, t2, t3, bd);
                bh[nh * 2][0] = t0; bh[nh * 2][1] = t1;
                bh[nh * 2 + 1][0] = t2; bh[nh * 2 + 1][1] = t3;
                LDSM4(t0, t1, t2, t3, bd + (G1_B_LO - G1_B_HI));
                bl[nh * 2][0] = t0; bl[nh * 2][1] = t1;
                bl[nh * 2 + 1][0] = t2; bl[nh * 2 + 1][1] = t3;
            }
#pragma unroll
            for (int mi = 0; mi < 4; mi++) {
#pragma unroll
                for (int ni = 0; ni < 4; ni++) {
                    MMA16816(acc[mi][ni], ah[mi], bh[ni]);
                    MMA16816(acc[mi][ni], ah[mi], bl[ni]);
                    MMA16816(acc[mi][ni], al[mi], bh[ni]);
                }
            }
        }
        __syncthreads();
    }

#pragma unroll
    for (int mi = 0; mi < 4; mi++) {
#pragma unroll
        for (int ni = 0; ni < 4; ni++) {
            int grow = row0 + wm * 64 + mi * 16 + (lane >> 2);
            int gcol = col0 + wn * 32 + ni * 8 + (lane & 3) * 2;
            if (grow < M) {
                float2 v = make_float2(acc[mi][ni][0], acc[mi][ni][1]);
                *(float2*)(g_z1 + (size_t)grow * 256 + gcol) = v;
            }
            if (grow + 8 < M) {
                float2 v = make_float2(acc[mi][ni][2], acc[mi][ni][3]);
                *(float2*)(g_z1 + (size_t)(grow + 8) * 256 + gcol) = v;
            }
        }
    }

#pragma unroll
    for (int ni = 0; ni < 4; ni++) {
#pragma unroll
        for (int jj = 0; jj < 2; jj++) {
            float s = 0.f, s2 = 0.f;
#pragma unroll
            for (int mi = 0; mi < 4; mi++) {
                float v0 = acc[mi][ni][jj], v1 = acc[mi][ni][jj + 2];
                s += v0 + v1; s2 += v0 * v0 + v1 * v1;
            }
#pragma unroll
            for (int o = 4; o <= 16; o <<= 1) {
                s  += __shfl_xor_sync(FULL, s, o);
                s2 += __shfl_xor_sync(FULL, s2, o);
            }
            if ((lane >> 2) == 0) {
                int col = col0 + wn * 32 + ni * 8 + (lane & 3) * 2 + jj;
                atomicAdd(&g_stats1[col], s);
                atomicAdd(&g_stats1[256 + col], s2);
            }
        }
    }
}

__global__ void k_bnp(const float* __restrict__ g, const float* __restrict__ b,
                      int C, float invM, int which) {
    int c = blockIdx.x * blockDim.x + threadIdx.x;
    if (c < C) {
        const float* st = which ? g_stats2 : g_stats1;
        float* sc = which ? g_bn2sc : g_bn1sc;
        float* sh = which ? g_bn2sh : g_bn1sh;
        float mu  = st[c] * invM;
        float var = st[C + c] * invM - mu * mu;
        float s = g[c] * rsqrtf(var + 0.001f);
        sc[c] = s;
        sh[c] = b[c] - mu * s;
    }
}

// ---------------- GEMM2 (mma.sync bf16 hi/lo): out = relu(bn1(z1)) @ W2 + fused bn2 stats ----------------
// block 128 rows x 64 cols; K=256 in 4 chunks of 64; bn1+relu+split applied in A-load
#define G2_PITCHB  144
#define G2_A_HI    0
#define G2_A_LO    18432
#define G2_B_HI    36864
#define G2_B_LO    46080
#define G2_SMEM    55296

__global__ void __launch_bounds__(256, 1)
k_gemm2_mma(float* __restrict__ out, int M) {
    extern __shared__ __align__(16) char dsm2[];
    uint32_t sbase = smem_u32(dsm2);
    __shared__ float ss[128];
    const unsigned FULL = 0xffffffffu;

    int tid  = threadIdx.x;
    int lane = tid & 31;
    int wid  = tid >> 5;          // warp owns rows wid*16..+15
    int row0 = blockIdx.x * 128;

    if (tid < 128) ss[tid] = 0.f;

    float acc[8][4] = {};

    uint32_t aRow  = (uint32_t)(wid * 16 + (lane & 15));
    uint32_t aColB = (uint32_t)((lane >> 4) * 16);
    uint32_t bRowB = (uint32_t)(((lane >> 4) & 1) * 8 + (lane & 7));
    uint32_t bColB = (uint32_t)(((lane >> 3) & 1) * 16);

    for (int c = 0; c < 4; c++) {
        __syncthreads();   // previous chunk's mma reads done before overwrite
        // ---- A: load z1 fp32, bn1+relu, split hi/lo to smem ----
        {
            int f4 = tid & 3;
#pragma unroll
            for (int half = 0; half < 2; half++) {
                int r = (tid >> 2) + half * 64;
                int gr = row0 + r;
#pragma unroll
                for (int q = 0; q < 4; q++) {
                    int col = (f4 * 4 + q) * 4;   // 0..60 step 4
                    float4 av = make_float4(0.f, 0.f, 0.f, 0.f);
                    if (gr < M) {
                        av = *(const float4*)(g_z1 + (size_t)gr * 256 + c * 64 + col);
                        float4 sc = *(const float4*)(g_bn1sc + c * 64 + col);
                        float4 sh = *(const float4*)(g_bn1sh + c * 64 + col);
                        av.x = fmaxf(av.x * sc.x + sh.x, 0.f);
                        av.y = fmaxf(av.y * sc.y + sh.y, 0.f);
                        av.z = fmaxf(av.z * sc.z + sh.z, 0.f);
                        av.w = fmaxf(av.w * sc.w + sh.w, 0.f);
                    }
                    __nv_bfloat162 h01 = __floats2bfloat162_rn(av.x, av.y);
                    __nv_bfloat162 h23 = __floats2bfloat162_rn(av.z, av.w);
                    float l0 = av.x - __bfloat162float(__low2bfloat16(h01));
                    float l1 = av.y - __bfloat162float(__high2bfloat16(h01));
                    float l2 = av.z - __bfloat162float(__low2bfloat16(h23));
                    float l3 = av.w - __bfloat162float(__high2bfloat16(h23));
                    __nv_bfloat162 lo01 = __floats2bfloat162_rn(l0, l1);
                    __nv_bfloat162 lo23 = __floats2bfloat162_rn(l2, l3);
                    uint32_t off = (uint32_t)(r * G2_PITCHB + col * 2);
                    *(uint2*)(dsm2 + G2_A_HI + off) = make_uint2(*(uint32_t*)&h01, *(uint32_t*)&h23);
                    *(uint2*)(dsm2 + G2_A_LO + off) = make_uint2(*(uint32_t*)&lo01, *(uint32_t*)&lo23);
                }
            }
        }
        // ---- B: copy w2t chunk (64 n x 64 k bf16) hi/lo ----
        {
            int n = tid >> 2;
            int kg = (tid & 3) * 16;  // 16 bf16 = 32B
            const uint4* gh = (const uint4*)(g_w2t_hi + (size_t)n * 256 + c * 64 + kg);
            const uint4* gl = (const uint4*)(g_w2t_lo + (size_t)n * 256 + c * 64 + kg);
            uint32_t off = (uint32_t)(n * G2_PITCHB + kg * 2);
            *(uint4*)(dsm2 + G2_B_HI + off)      = gh[0];
            *(uint4*)(dsm2 + G2_B_HI + off + 16) = gh[1];
            *(uint4*)(dsm2 + G2_B_LO + off)      = gl[0];
            *(uint4*)(dsm2 + G2_B_LO + off + 16) = gl[1];
        }
        __syncthreads();

#pragma unroll
        for (int kk = 0; kk < 4; kk++) {
            uint32_t kb = (uint32_t)(kk * 32);
            uint32_t ah[4], al[4];
            {
                uint32_t ad = sbase + G2_A_HI + aRow * G2_PITCHB + kb + aColB;
                LDSM4(ah[0], ah[1], ah[2], ah[3], ad);
                LDSM4(al[0], al[1], al[2], al[3], ad + (G2_A_LO - G2_A_HI));
            }
            uint32_t bh[8][2], bl[8][2];
#pragma unroll
            for (int nh = 0; nh < 4; nh++) {
                uint32_t bd = sbase + G2_B_HI + (nh * 16 + bRowB) * G2_PITCHB + kb + bColB;
                uint32_t t0, t1, t2, t3;
                LDSM4(t0, t1, t2, t3, bd);
                bh[nh * 2][0] = t0; bh[nh * 2][1] = t1;
                bh[nh * 2 + 1][0] = t2; bh[nh * 2 + 1][1] = t3;
                LDSM4(t0, t1, t2, t3, bd + (G2_B_LO - G2_B_HI));
                bl[nh * 2][0] = t0; bl[nh * 2][1] = t1;
                bl[nh * 2 + 1][0] = t2; bl[nh * 2 + 1][1] = t3;
            }
#pragma unroll
            for (int ni = 0; ni < 8; ni++) {
                MMA16816(acc[ni], ah, bh[ni]);
                MMA16816(acc[ni], ah, bl[ni]);
                MMA16816(acc[ni], al, bh[ni]);
            }
        }
    }

    // epilogue: stores
    int grow = row0 + wid * 16 + (lane >> 2);
#pragma unroll
    for (int ni = 0; ni < 8; ni++) {
        int gcol = ni * 8 + (lane & 3) * 2;
        if (grow < M)
            *(float2*)(out + (size_t)grow * 64 + gcol) = make_float2(acc[ni][0], acc[ni][1]);
        if (grow + 8 < M)
            *(float2*)(out + (size_t)(grow + 8) * 64 + gcol) = make_float2(acc[ni][2], acc[ni][3]);
    }

    // fused bn2 stats (OOB rows contributed zeros)
#pragma unroll
    for (int ni = 0; ni < 8; ni++) {
#pragma unroll
        for (int jj = 0; jj < 2; jj++) {
            float s = acc[ni][jj] + acc[ni][jj + 2];
            float s2 = acc[ni][jj] * acc[ni][jj] + acc[ni][jj + 2] * acc[ni][jj + 2];
#pragma unroll
            for (int o = 4; o <= 16; o <<= 1) {
                s  += __shfl_xor_sync(FULL, s, o);
                s2 += __shfl_xor_sync(FULL, s2, o);
            }
            if ((lane >> 2) == 0) {
                int col = ni * 8 + (lane & 3) * 2 + jj;
                atomicAdd(&ss[col], s);
                atomicAdd(&ss[64 + col], s2);
            }
        }
    }
    __syncthreads();
    if (tid < 128) atomicAdd(&g_stats2[tid], ss[tid]);
}

__global__ void k_final(float* __restrict__ out, int n) {
    int i = blockIdx.x * blockDim.x + threadIdx.x;
    if (i < n) {
        int c = i & 63;
        out[i] = fmaxf(out[i] * g_bn2sc[c] + g_bn2sh[c], 0.f);
    }
}

// ---------------- launcher ----------------
extern "C" void kernel_launch(void* const* d_in, const int* in_sizes, int n_in,
                              void* d_out, int out_size) {
    const float* vf      = (const float*)d_in[0];
    const int*   coords  = (const int*)d_in[1];
    const int*   inv     = (const int*)d_in[3];
    const int*   cnt     = (const int*)d_in[4];
    const float* up_w1   = (const float*)d_in[5];
    const float* up_b1   = (const float*)d_in[6];
    const float* up_w2   = (const float*)d_in[7];
    const float* up_b2   = (const float*)d_in[8];
    const float* ca_w1   = (const float*)d_in[9];
    const float* ca_w2   = (const float*)d_in[10];
    const float* sa_conv = (const float*)d_in[11];
    const float* bs_w1   = (const float*)d_in[12];
    const float* bn1_g   = (const float*)d_in[13];
    const float* bn1_b   = (const float*)d_in[14];
    const float* bs_w2   = (const float*)d_in[15];
    const float* bn2_g   = (const float*)d_in[16];
    const float* bn2_b   = (const float*)d_in[17];

    int Nv = in_sizes[0] / 5;
    int U  = in_sizes[2];
    int M  = out_size / 64;
    if (M <= 0) return;

    int nwin = U * 8;
    k_init<<<(nwin + 255) / 256, 256>>>(nwin);
    k_scatter<<<(Nv + 255) / 256, 256>>>(coords, inv, Nv);

    int NB = (U + 1023) / 1024;
    k_count<<<NB, 256>>>(cnt, U);
    k_scan2<<<1, 256>>>(NB);
    k_compact<<<NB, 256>>>(cnt, U);

    k_prepw<<<512, 256>>>(bs_w1);
    k_prepw2<<<64, 256>>>(bs_w2);
    k_rows2<<<(M + 63) / 64, 256>>>(vf, up_w1, up_b1, up_w2, up_b2,
                                    ca_w1, ca_w2, sa_conv, M);

    {
        int dynsmem = 2 * G1_STAGE;
        cudaFuncSetAttribute(k_gemm1_mma, cudaFuncAttributeMaxDynamicSharedMemorySize, dynsmem);
        dim3 g1((M + 127) / 128, 2);
        k_gemm1_mma<<<g1, 256, dynsmem>>>(M);
    }
    k_bnp<<<1, 256>>>(bn1_g, bn1_b, 256, 1.f / (float)M, 0);

    {
        cudaFuncSetAttribute(k_gemm2_mma, cudaFuncAttributeMaxDynamicSharedMemorySize, G2_SMEM);
        k_gemm2_mma<<<(M + 127) / 128, 256, G2_SMEM>>>((float*)d_out, M);
    }
    k_bnp<<<1, 64>>>(bn2_g, bn2_b, 64, 1.f / (float)M, 1);
    k_final<<<(M * 64 + 255) / 256, 256>>>((float*)d_out, M * 64);
}

// round 8
// speedup vs baseline: 3.9952x; 1.3628x over previous
#include <cuda_runtime.h>
#include <cuda_bf16.h>
#include <cuda_fp16.h>
#include <math.h>
#include <stdint.h>

// ---------------- static scratch (allocation-free) ----------------
#define UMAX 200000
__device__ int   g_winner[UMAX * 8];
__device__ int   g_selrows[UMAX];
__device__ int   g_bsum[256];
__device__ __align__(16) __half g_flat_h[(size_t)UMAX * 512];
__device__ __align__(16) __half g_wt_h[256 * 512];
__device__ __align__(16) __nv_bfloat16 g_w2t_hi[64 * 256];
__device__ __align__(16) __nv_bfloat16 g_w2t_lo[64 * 256];
__device__ __align__(16) float g_z1[(size_t)UMAX * 256];
__device__ __align__(16) float g_stats1[512];   // sum[256] | sumsq[256]
__device__ __align__(16) float g_stats2[128];   // sum[64]  | sumsq[64]
__device__ __align__(16) float g_bn1sc[256];
__device__ __align__(16) float g_bn1sh[256];
__device__ __align__(16) float g_bn2sc[64];
__device__ __align__(16) float g_bn2sh[64];

__device__ __forceinline__ uint32_t smem_u32(const void* p) {
    uint32_t a;
    asm("{ .reg .u64 t; cvta.to.shared.u64 t, %1; cvt.u32.u64 %0, t; }" : "=r"(a) : "l"(p));
    return a;
}

// ---------------- init ----------------
__global__ void k_init(int nwin) {
    int i = blockIdx.x * blockDim.x + threadIdx.x;
    if (i < nwin) g_winner[i] = -1;
    if (i < 512)  g_stats1[i] = 0.f;
    if (i < 128)  g_stats2[i] = 0.f;
}

// ---------------- scatter: last-write-wins via max voxel index ----------------
__global__ void k_scatter(const int* __restrict__ coords, const int* __restrict__ inv, int Nv) {
    int i = blockIdx.x * blockDim.x + threadIdx.x;
    if (i < Nv) {
        int z = coords[(size_t)i * 4 + 1];
        int u = inv[i];
        atomicMax(&g_winner[(size_t)u * 8 + z], i);
    }
}

// ---------------- ordered compaction of rows with cnt>=2 ----------------
__global__ void k_count(const int* __restrict__ cnt, int U) {
    __shared__ int s[256];
    int base = blockIdx.x * 1024;
    int c = 0;
    for (int t = threadIdx.x; t < 1024; t += 256) {
        int u = base + t;
        if (u < U && cnt[u] >= 2) c++;
    }
    s[threadIdx.x] = c;
    __syncthreads();
    for (int o = 128; o > 0; o >>= 1) {
        if (threadIdx.x < o) s[threadIdx.x] += s[threadIdx.x + o];
        __syncthreads();
    }
    if (threadIdx.x == 0) g_bsum[blockIdx.x] = s[0];
}

__global__ void k_scan2(int nb) {
    __shared__ int s[256];
    int t = threadIdx.x;
    int v = (t < nb) ? g_bsum[t] : 0;
    s[t] = v;
    __syncthreads();
    for (int o = 1; o < 256; o <<= 1) {
        int u = (t >= o) ? s[t - o] : 0;
        __syncthreads();
        s[t] += u;
        __syncthreads();
    }
    if (t < nb) g_bsum[t] = s[t] - v;   // exclusive
}

__global__ void k_compact(const int* __restrict__ cnt, int U) {
    __shared__ int s[256];
    int tid = threadIdx.x;
    int base = blockIdx.x * 1024 + tid * 4;
    int flags[4]; int c = 0;
    for (int q = 0; q < 4; q++) {
        int u = base + q;
        flags[q] = (u < U && cnt[u] >= 2) ? 1 : 0;
        c += flags[q];
    }
    s[tid] = c;
    __syncthreads();
    for (int o = 1; o < 256; o <<= 1) {
        int v = (tid >= o) ? s[tid - o] : 0;
        __syncthreads();
        s[tid] += v;
        __syncthreads();
    }
    int off = g_bsum[blockIdx.x] + s[tid] - c;
    for (int q = 0; q < 4; q++) {
        if (flags[q]) g_selrows[off++] = base + q;
    }
}

// ---------------- weight transpose: Wt[n][k] fp16 ----------------
__global__ void k_prepw(const float* __restrict__ W) {
    int i = blockIdx.x * 256 + threadIdx.x;   // 131072 total
    int n = i >> 9, k = i & 511;
    g_wt_h[i] = __float2half(W[(size_t)k * 256 + n]);
}

__global__ void k_prepw2(const float* __restrict__ W) {
    int i = blockIdx.x * 256 + threadIdx.x;   // 16384 total
    int n = i >> 8, k = i & 255;
    float w = W[(size_t)k * 64 + n];
    __nv_bfloat16 hi = __float2bfloat16(w);
    float lo = w - __bfloat162float(hi);
    g_w2t_hi[i] = hi;
    g_w2t_lo[i] = __float2bfloat16(lo);
}

// ---------------- fused per-row (warp-per-row): slot MLP + CBAM + flatten ----------------
__global__ void __launch_bounds__(256)
k_rows2(const float* __restrict__ vf,
        const float* __restrict__ w1, const float* __restrict__ b1,
        const float* __restrict__ w2g, const float* __restrict__ b2,
        const float* __restrict__ caw1, const float* __restrict__ caw2,
        const float* __restrict__ saconv, int M)
{
    __shared__ float sw1[160], sb1[32], sb2[64];
    __shared__ float scw1[512], scw2[512], sconv[16];
    __shared__ float sfeatw[8][40];
    __shared__ __align__(16) float shidw[8][8][32];

    const unsigned FULL = 0xffffffffu;
    int tid  = threadIdx.x;
    int wid  = tid >> 5;
    int lane = tid & 31;

    for (int i = tid; i < 160; i += 256) sw1[i] = w1[i];
    if (tid < 32) sb1[tid] = b1[tid];
    if (tid < 64) sb2[tid] = b2[tid];
    for (int i = tid; i < 512; i += 256) scw1[i] = caw1[i];
    for (int i = tid; i < 512; i += 256) scw2[i] = caw2[i];
    if (tid < 14) sconv[tid] = saconv[tid];

    float w2a[32], w2b[32];
#pragma unroll
    for (int k = 0; k < 32; k++) {
        w2a[k] = w2g[k * 64 + lane];
        w2b[k] = w2g[k * 64 + lane + 32];
    }
    __syncthreads();

    for (int r = 0; r < 8; r++) {
        int j = blockIdx.x * 64 + wid * 8 + r;
        if (j >= M) break;
        int u = g_selrows[j];
        int wv = (lane < 8) ? g_winner[(size_t)u * 8 + lane] : -1;

#pragma unroll
        for (int q = 0; q < 2; q++) {
            int t = lane + q * 32;
            int valid = (t < 40);
            int zz = valid ? (t / 5) : 0;
            int f  = t - zz * 5;
            int w = __shfl_sync(FULL, wv, zz);
            if (valid) sfeatw[wid][t] = (w >= 0) ? vf[(size_t)w * 5 + f] : 0.f;
        }
        __syncwarp();

#pragma unroll
        for (int z = 0; z < 8; z++) {
            float a = sb1[lane];
#pragma unroll
            for (int f = 0; f < 5; f++) a += sfeatw[wid][z * 5 + f] * sw1[f * 32 + lane];
            shidw[wid][z][lane] = fmaxf(a, 0.f);
        }
        __syncwarp();

        float x0[8], x1[8];
#pragma unroll
        for (int z = 0; z < 8; z++) {
            float a0 = sb2[lane], a1 = sb2[lane + 32];
            const float* hz = &shidw[wid][z][0];
#pragma unroll
            for (int k4 = 0; k4 < 8; k4++) {
                float4 h = *(const float4*)(hz + k4 * 4);
                a0 += h.x * w2a[k4 * 4] + h.y * w2a[k4 * 4 + 1] + h.z * w2a[k4 * 4 + 2] + h.w * w2a[k4 * 4 + 3];
                a1 += h.x * w2b[k4 * 4] + h.y * w2b[k4 * 4 + 1] + h.z * w2b[k4 * 4 + 2] + h.w * w2b[k4 * 4 + 3];
            }
            x0[z] = a0; x1[z] = a1;
        }

        float m0 = 0.f, m1 = 0.f, q0 = -3.4e38f, q1 = -3.4e38f;
#pragma unroll
        for (int z = 0; z < 8; z++) {
            m0 += x0[z]; m1 += x1[z];
            q0 = fmaxf(q0, x0[z]); q1 = fmaxf(q1, x1[z]);
        }
        m0 *= 0.125f; m1 *= 0.125f;

        float s8[8];
#pragma unroll
        for (int r8 = 0; r8 < 8; r8++) {
            float pm = m0 * scw1[lane * 8 + r8] + m1 * scw1[(lane + 32) * 8 + r8];
            float px = q0 * scw1[lane * 8 + r8] + q1 * scw1[(lane + 32) * 8 + r8];
#pragma unroll
            for (int o = 16; o > 0; o >>= 1) {
                pm += __shfl_xor_sync(FULL, pm, o);
                px += __shfl_xor_sync(FULL, px, o);
            }
            s8[r8] = fmaxf(pm, 0.f) + fmaxf(px, 0.f);
        }

        float a0 = 0.f, a1 = 0.f;
#pragma unroll
        for (int r8 = 0; r8 < 8; r8++) {
            a0 += s8[r8] * scw2[r8 * 64 + lane];
            a1 += s8[r8] * scw2[r8 * 64 + lane + 32];
        }
        float ca0 = 1.f / (1.f + expf(-a0));
        float ca1 = 1.f / (1.f + expf(-a1));
#pragma unroll
        for (int z = 0; z < 8; z++) { x0[z] *= ca0; x1[z] *= ca1; }

        float szm[8], szx[8];
#pragma unroll
        for (int z = 0; z < 8; z++) {
            float s = x0[z] + x1[z];
            float m = fmaxf(x0[z], x1[z]);
#pragma unroll
            for (int o = 16; o > 0; o >>= 1) {
                s += __shfl_xor_sync(FULL, s, o);
                m = fmaxf(m, __shfl_xor_sync(FULL, m, o));
            }
            szm[z] = s * (1.f / 64.f);
            szx[z] = m;
        }

        float sav = 0.f;
        if (lane < 8) {
            float acc = 0.f;
#pragma unroll
            for (int t = 0; t < 7; t++) {
                int p = lane + t - 3;
                if (p >= 0 && p < 8) acc += szm[p] * sconv[t] + szx[p] * sconv[7 + t];
            }
            sav = 1.f / (1.f + expf(-acc));
        }
        float sa[8];
#pragma unroll
        for (int z = 0; z < 8; z++) sa[z] = __shfl_sync(FULL, sav, z);

        size_t base = (size_t)j * 512;
        uint32_t ph[4];
#pragma unroll
        for (int z2 = 0; z2 < 4; z2++) {
            __half2 h2 = __floats2half2_rn(x0[2 * z2] * sa[2 * z2], x0[2 * z2 + 1] * sa[2 * z2 + 1]);
            ph[z2] = *(uint32_t*)&h2;
        }
        *(uint4*)&g_flat_h[base + lane * 8] = *(uint4*)ph;
#pragma unroll
        for (int z2 = 0; z2 < 4; z2++) {
            __half2 h2 = __floats2half2_rn(x1[2 * z2] * sa[2 * z2], x1[2 * z2 + 1] * sa[2 * z2 + 1]);
            ph[z2] = *(uint32_t*)&h2;
        }
        *(uint4*)&g_flat_h[base + (lane + 32) * 8] = *(uint4*)ph;
        __syncwarp();
    }
}

// ---------------- common mma macros ----------------
#define LDSM4(R0, R1, R2, R3, ADDR) \
    asm volatile("ldmatrix.sync.aligned.m8n8.x4.shared.b16 {%0,%1,%2,%3}, [%4];" \
                 : "=r"(R0), "=r"(R1), "=r"(R2), "=r"(R3) : "r"(ADDR))

#define MMA16816BF(D, A, B) \
    asm volatile("mma.sync.aligned.m16n8k16.row.col.f32.bf16.bf16.f32 " \
                 "{%0,%1,%2,%3}, {%4,%5,%6,%7}, {%8,%9}, {%0,%1,%2,%3};" \
                 : "+f"((D)[0]), "+f"((D)[1]), "+f"((D)[2]), "+f"((D)[3]) \
                 : "r"((A)[0]), "r"((A)[1]), "r"((A)[2]), "r"((A)[3]), \
                   "r"((B)[0]), "r"((B)[1]))

#define MMA16816F16(D, A, B) \
    asm volatile("mma.sync.aligned.m16n8k16.row.col.f32.f16.f16.f32 " \
                 "{%0,%1,%2,%3}, {%4,%5,%6,%7}, {%8,%9}, {%0,%1,%2,%3};" \
                 : "+f"((D)[0]), "+f"((D)[1]), "+f"((D)[2]), "+f"((D)[3]) \
                 : "r"((A)[0]), "r"((A)[1]), "r"((A)[2]), "r"((A)[3]), \
                   "r"((B)[0]), "r"((B)[1]))

__device__ __forceinline__ void cp16(uint32_t saddr, const void* gaddr, uint32_t sz) {
    asm volatile("cp.async.cg.shared.global [%0], [%1], 16, %2;"
                 :: "r"(saddr), "l"(gaddr), "r"(sz));
}

// ---------------- GEMM1 (mma.sync fp16 single-pass) + fused bn1 stats ----------------
#define G1_PITCHB  144
#define G1_A_OFF   0
#define G1_B_OFF   18432
#define G1_STAGE   36864

__global__ void __launch_bounds__(256, 2)
k_gemm1_mma(int M) {
    extern __shared__ __align__(16) char dsm[];
    uint32_t sbase = smem_u32(dsm);
    const unsigned FULL = 0xffffffffu;

    int tid  = threadIdx.x;
    int lane = tid & 31;
    int wid  = tid >> 5;
    int wm = wid & 1;
    int wn = wid >> 1;
    int row0 = blockIdx.x * 128;
    int col0 = blockIdx.y * 128;

    int li_r  = tid >> 3;
    int li_c8 = tid & 7;

    float acc[4][4][4] = {};

    auto load_chunk = [&](int c) {
        uint32_t st = sbase + (uint32_t)(c & 1) * G1_STAGE;
#pragma unroll
        for (int it = 0; it < 4; it++) {
            int r = li_r + it * 32;
            int gr = row0 + r;
            uint32_t soff = (uint32_t)(r * G1_PITCHB + li_c8 * 16);
            size_t goff = (size_t)gr * 512 + c * 64 + li_c8 * 8;
            uint32_t sz = (gr < M) ? 16u : 0u;
            cp16(st + G1_A_OFF + soff, g_flat_h + goff, sz);
            int n = col0 + r;
            size_t boff = (size_t)n * 512 + c * 64 + li_c8 * 8;
            cp16(st + G1_B_OFF + soff, g_wt_h + boff, 16u);
        }
        asm volatile("cp.async.commit_group;");
    };

    load_chunk(0);

    uint32_t aRow  = (uint32_t)(wm * 64 + (lane & 15));
    uint32_t aColB = (uint32_t)((lane >> 4) * 16);
    uint32_t bRow  = (uint32_t)(wn * 32 + ((lane >> 4) & 1) * 8 + (lane & 7));
    uint32_t bColB = (uint32_t)(((lane >> 3) & 1) * 16);

    for (int c = 0; c < 8; c++) {
        if (c < 7) load_chunk(c + 1);
        if (c < 7) { asm volatile("cp.async.wait_group 1;"); }
        else       { asm volatile("cp.async.wait_group 0;"); }
        __syncthreads();

        uint32_t st = sbase + (uint32_t)(c & 1) * G1_STAGE;
#pragma unroll
        for (int kk = 0; kk < 4; kk++) {
            uint32_t kb = (uint32_t)(kk * 32);
            uint32_t ah[4][4];
#pragma unroll
            for (int mi = 0; mi < 4; mi++) {
                uint32_t ad = st + G1_A_OFF + (aRow + mi * 16) * G1_PITCHB + kb + aColB;
                LDSM4(ah[mi][0], ah[mi][1], ah[mi][2], ah[mi][3], ad);
            }
            uint32_t bh[4][2];
#pragma unroll
            for (int nh = 0; nh < 2; nh++) {
                uint32_t bd = st + G1_B_OFF + (bRow + nh * 16) * G1_PITCHB + kb + bColB;
                uint32_t t0, t1, t2, t3;
                LDSM4(t0, t1, t2, t3, bd);
                bh[nh * 2][0] = t0; bh[nh * 2][1] = t1;
                bh[nh * 2 + 1][0] = t2; bh[nh * 2 + 1][1] = t3;
            }
#pragma unroll
            for (int mi = 0; mi < 4; mi++) {
#pragma unroll
                for (int ni = 0; ni < 4; ni++) {
                    MMA16816F16(acc[mi][ni], ah[mi], bh[ni]);
                }
            }
        }
        __syncthreads();
    }

#pragma unroll
    for (int mi = 0; mi < 4; mi++) {
#pragma unroll
        for (int ni = 0; ni < 4; ni++) {
            int grow = row0 + wm * 64 + mi * 16 + (lane >> 2);
            int gcol = col0 + wn * 32 + ni * 8 + (lane & 3) * 2;
            if (grow < M) {
                float2 v = make_float2(acc[mi][ni][0], acc[mi][ni][1]);
                *(float2*)(g_z1 + (size_t)grow * 256 + gcol) = v;
            }
            if (grow + 8 < M) {
                float2 v = make_float2(acc[mi][ni][2], acc[mi][ni][3]);
                *(float2*)(g_z1 + (size_t)(grow + 8) * 256 + gcol) = v;
            }
        }
    }

#pragma unroll
    for (int ni = 0; ni < 4; ni++) {
#pragma unroll
        for (int jj = 0; jj < 2; jj++) {
            float s = 0.f, s2 = 0.f;
#pragma unroll
            for (int mi = 0; mi < 4; mi++) {
                float v0 = acc[mi][ni][jj], v1 = acc[mi][ni][jj + 2];
                s += v0 + v1; s2 += v0 * v0 + v1 * v1;
            }
#pragma unroll
            for (int o = 4; o <= 16; o <<= 1) {
                s  += __shfl_xor_sync(FULL, s, o);
                s2 += __shfl_xor_sync(FULL, s2, o);
            }
            if ((lane >> 2) == 0) {
                int col = col0 + wn * 32 + ni * 8 + (lane & 3) * 2 + jj;
                atomicAdd(&g_stats1[col], s);
                atomicAdd(&g_stats1[256 + col], s2);
            }
        }
    }
}

__global__ void k_bnp(const float* __restrict__ g, const float* __restrict__ b,
                      int C, float invM, int which) {
    int c = blockIdx.x * blockDim.x + threadIdx.x;
    if (c < C) {
        const float* st = which ? g_stats2 : g_stats1;
        float* sc = which ? g_bn2sc : g_bn1sc;
        float* sh = which ? g_bn2sh : g_bn1sh;
        float mu  = st[c] * invM;
        float var = st[C + c] * invM - mu * mu;
        float s = g[c] * rsqrtf(var + 0.001f);
        sc[c] = s;
        sh[c] = b[c] - mu * s;
    }
}

// ---------------- GEMM2 (mma.sync bf16 hi/lo): out = relu(bn1(z1)) @ W2 + fused bn2 stats ----------------
#define G2_PITCHB  144
#define G2_A_HI    0
#define G2_A_LO    18432
#define G2_B_HI    36864
#define G2_B_LO    46080
#define G2_SMEM    55296

__global__ void __launch_bounds__(256, 1)
k_gemm2_mma(float* __restrict__ out, int M) {
    extern __shared__ __align__(16) char dsm2[];
    uint32_t sbase = smem_u32(dsm2);
    __shared__ float ss[128];
    const unsigned FULL = 0xffffffffu;

    int tid  = threadIdx.x;
    int lane = tid & 31;
    int wid  = tid >> 5;
    int row0 = blockIdx.x * 128;

    if (tid < 128) ss[tid] = 0.f;

    float acc[8][4] = {};

    uint32_t aRow  = (uint32_t)(wid * 16 + (lane & 15));
    uint32_t aColB = (uint32_t)((lane >> 4) * 16);
    uint32_t bRowB = (uint32_t)(((lane >> 4) & 1) * 8 + (lane & 7));
    uint32_t bColB = (uint32_t)(((lane >> 3) & 1) * 16);

    for (int c = 0; c < 4; c++) {
        __syncthreads();
        {
            int f4 = tid & 3;
#pragma unroll
            for (int half = 0; half < 2; half++) {
                int r = (tid >> 2) + half * 64;
                int gr = row0 + r;
#pragma unroll
                for (int q = 0; q < 4; q++) {
                    int col = (f4 * 4 + q) * 4;
                    float4 av = make_float4(0.f, 0.f, 0.f, 0.f);
                    if (gr < M) {
                        av = *(const float4*)(g_z1 + (size_t)gr * 256 + c * 64 + col);
                        float4 sc = *(const float4*)(g_bn1sc + c * 64 + col);
                        float4 sh = *(const float4*)(g_bn1sh + c * 64 + col);
                        av.x = fmaxf(av.x * sc.x + sh.x, 0.f);
                        av.y = fmaxf(av.y * sc.y + sh.y, 0.f);
                        av.z = fmaxf(av.z * sc.z + sh.z, 0.f);
                        av.w = fmaxf(av.w * sc.w + sh.w, 0.f);
                    }
                    __nv_bfloat162 h01 = __floats2bfloat162_rn(av.x, av.y);
                    __nv_bfloat162 h23 = __floats2bfloat162_rn(av.z, av.w);
                    float l0 = av.x - __bfloat162float(__low2bfloat16(h01));
                    float l1 = av.y - __bfloat162float(__high2bfloat16(h01));
                    float l2 = av.z - __bfloat162float(__low2bfloat16(h23));
                    float l3 = av.w - __bfloat162float(__high2bfloat16(h23));
                    __nv_bfloat162 lo01 = __floats2bfloat162_rn(l0, l1);
                    __nv_bfloat162 lo23 = __floats2bfloat162_rn(l2, l3);
                    uint32_t off = (uint32_t)(r * G2_PITCHB + col * 2);
                    *(uint2*)(dsm2 + G2_A_HI + off) = make_uint2(*(uint32_t*)&h01, *(uint32_t*)&h23);
                    *(uint2*)(dsm2 + G2_A_LO + off) = make_uint2(*(uint32_t*)&lo01, *(uint32_t*)&lo23);
                }
            }
        }
        {
            int n = tid >> 2;
            int kg = (tid & 3) * 16;
            const uint4* gh = (const uint4*)(g_w2t_hi + (size_t)n * 256 + c * 64 + kg);
            const uint4* gl = (const uint4*)(g_w2t_lo + (size_t)n * 256 + c * 64 + kg);
            uint32_t off = (uint32_t)(n * G2_PITCHB + kg * 2);
            *(uint4*)(dsm2 + G2_B_HI + off)      = gh[0];
            *(uint4*)(dsm2 + G2_B_HI + off + 16) = gh[1];
            *(uint4*)(dsm2 + G2_B_LO + off)      = gl[0];
            *(uint4*)(dsm2 + G2_B_LO + off + 16) = gl[1];
        }
        __syncthreads();

#pragma unroll
        for (int kk = 0; kk < 4; kk++) {
            uint32_t kb = (uint32_t)(kk * 32);
            uint32_t ah[4], al[4];
            {
                uint32_t ad = sbase + G2_A_HI + aRow * G2_PITCHB + kb + aColB;
                LDSM4(ah[0], ah[1], ah[2], ah[3], ad);
                LDSM4(al[0], al[1], al[2], al[3], ad + (G2_A_LO - G2_A_HI));
            }
            uint32_t bh[8][2], bl[8][2];
#pragma unroll
            for (int nh = 0; nh < 4; nh++) {
                uint32_t bd = sbase + G2_B_HI + (nh * 16 + bRowB) * G2_PITCHB + kb + bColB;
                uint32_t t0, t1, t2, t3;
                LDSM4(t0, t1, t2, t3, bd);
                bh[nh * 2][0] = t0; bh[nh * 2][1] = t1;
                bh[nh * 2 + 1][0] = t2; bh[nh * 2 + 1][1] = t3;
                LDSM4(t0, t1, t2, t3, bd + (G2_B_LO - G2_B_HI));
                bl[nh * 2][0] = t0; bl[nh * 2][1] = t1;
                bl[nh * 2 + 1][0] = t2; bl[nh * 2 + 1][1] = t3;
            }
#pragma unroll
            for (int ni = 0; ni < 8; ni++) {
                MMA16816BF(acc[ni], ah, bh[ni]);
                MMA16816BF(acc[ni], ah, bl[ni]);
                MMA16816BF(acc[ni], al, bh[ni]);
            }
        }
    }

    int grow = row0 + wid * 16 + (lane >> 2);
#pragma unroll
    for (int ni = 0; ni < 8; ni++) {
        int gcol = ni * 8 + (lane & 3) * 2;
        if (grow < M)
            *(float2*)(out + (size_t)grow * 64 + gcol) = make_float2(acc[ni][0], acc[ni][1]);
        if (grow + 8 < M)
            *(float2*)(out + (size_t)(grow + 8) * 64 + gcol) = make_float2(acc[ni][2], acc[ni][3]);
    }

#pragma unroll
    for (int ni = 0; ni < 8; ni++) {
#pragma unroll
        for (int jj = 0; jj < 2; jj++) {
            float s = acc[ni][jj] + acc[ni][jj + 2];
            float s2 = acc[ni][jj] * acc[ni][jj] + acc[ni][jj + 2] * acc[ni][jj + 2];
#pragma unroll
            for (int o = 4; o <= 16; o <<= 1) {
                s  += __shfl_xor_sync(FULL, s, o);
                s2 += __shfl_xor_sync(FULL, s2, o);
            }
            if ((lane >> 2) == 0) {
                int col = ni * 8 + (lane & 3) * 2 + jj;
                atomicAdd(&ss[col], s);
                atomicAdd(&ss[64 + col], s2);
            }
        }
    }
    __syncthreads();
    if (tid < 128) atomicAdd(&g_stats2[tid], ss[tid]);
}

__global__ void k_final(float* __restrict__ out, int n) {
    int i = blockIdx.x * blockDim.x + threadIdx.x;
    if (i < n) {
        int c = i & 63;
        out[i] = fmaxf(out[i] * g_bn2sc[c] + g_bn2sh[c], 0.f);
    }
}

// ---------------- launcher ----------------
extern "C" void kernel_launch(void* const* d_in, const int* in_sizes, int n_in,
                              void* d_out, int out_size) {
    const float* vf      = (const float*)d_in[0];
    const int*   coords  = (const int*)d_in[1];
    const int*   inv     = (const int*)d_in[3];
    const int*   cnt     = (const int*)d_in[4];
    const float* up_w1   = (const float*)d_in[5];
    const float* up_b1   = (const float*)d_in[6];
    const float* up_w2   = (const float*)d_in[7];
    const float* up_b2   = (const float*)d_in[8];
    const float* ca_w1   = (const float*)d_in[9];
    const float* ca_w2   = (const float*)d_in[10];
    const float* sa_conv = (const float*)d_in[11];
    const float* bs_w1   = (const float*)d_in[12];
    const float* bn1_g   = (const float*)d_in[13];
    const float* bn1_b   = (const float*)d_in[14];
    const float* bs_w2   = (const float*)d_in[15];
    const float* bn2_g   = (const float*)d_in[16];
    const float* bn2_b   = (const float*)d_in[17];

    int Nv = in_sizes[0] / 5;
    int U  = in_sizes[2];
    int M  = out_size / 64;
    if (M <= 0) return;

    int nwin = U * 8;
    k_init<<<(nwin + 255) / 256, 256>>>(nwin);
    k_scatter<<<(Nv + 255) / 256, 256>>>(coords, inv, Nv);

    int NB = (U + 1023) / 1024;
    k_count<<<NB, 256>>>(cnt, U);
    k_scan2<<<1, 256>>>(NB);
    k_compact<<<NB, 256>>>(cnt, U);

    k_prepw<<<512, 256>>>(bs_w1);
    k_prepw2<<<64, 256>>>(bs_w2);
    k_rows2<<<(M + 63) / 64, 256>>>(vf, up_w1, up_b1, up_w2, up_b2,
                                    ca_w1, ca_w2, sa_conv, M);

    {
        int dynsmem = 2 * G1_STAGE;
        cudaFuncSetAttribute(k_gemm1_mma, cudaFuncAttributeMaxDynamicSharedMemorySize, dynsmem);
        dim3 g1((M + 127) / 128, 2);
        k_gemm1_mma<<<g1, 256, dynsmem>>>(M);
    }
    k_bnp<<<1, 256>>>(bn1_g, bn1_b, 256, 1.f / (float)M, 0);

    {
        cudaFuncSetAttribute(k_gemm2_mma, cudaFuncAttributeMaxDynamicSharedMemorySize, G2_SMEM);
        k_gemm2_mma<<<(M + 127) / 128, 256, G2_SMEM>>>((float*)d_out, M);
    }
    k_bnp<<<1, 64>>>(bn2_g, bn2_b, 64, 1.f / (float)M, 1);
    k_final<<<(M * 64 + 255) / 256, 256>>>((float*)d_out, M * 64);
}

// round 9
// speedup vs baseline: 4.5283x; 1.1334x over previous
#include <cuda_runtime.h>
#include <cuda_bf16.h>
#include <cuda_fp16.h>
#include <math.h>
#include <stdint.h>

// ---------------- static scratch (allocation-free) ----------------
#define UMAX 200000
__device__ int   g_winner[UMAX * 8];
__device__ int   g_selrows[UMAX];
__device__ int   g_bsum[256];
__device__ __align__(16) __half g_flat_h[(size_t)UMAX * 512];
__device__ __align__(16) __half g_wt_h[256 * 512];
__device__ __align__(16) __half g_w2t_h[64 * 256];
__device__ __align__(16) __half g_z1h[(size_t)UMAX * 256];
__device__ __align__(16) float g_stats1[512];   // sum[256] | sumsq[256]
__device__ __align__(16) float g_stats2[128];   // sum[64]  | sumsq[64]
__device__ __align__(16) float g_bn1sc[256];
__device__ __align__(16) float g_bn1sh[256];
__device__ __align__(16) float g_bn2sc[64];
__device__ __align__(16) float g_bn2sh[64];

__device__ __forceinline__ uint32_t smem_u32(const void* p) {
    uint32_t a;
    asm("{ .reg .u64 t; cvta.to.shared.u64 t, %1; cvt.u32.u64 %0, t; }" : "=r"(a) : "l"(p));
    return a;
}

// ---------------- init ----------------
__global__ void k_init(int nwin) {
    int i = blockIdx.x * blockDim.x + threadIdx.x;
    if (i < nwin) g_winner[i] = -1;
    if (i < 512)  g_stats1[i] = 0.f;
    if (i < 128)  g_stats2[i] = 0.f;
}

// ---------------- scatter: last-write-wins via max voxel index ----------------
__global__ void k_scatter(const int* __restrict__ coords, const int* __restrict__ inv, int Nv) {
    int i = blockIdx.x * blockDim.x + threadIdx.x;
    if (i < Nv) {
        int z = coords[(size_t)i * 4 + 1];
        int u = inv[i];
        atomicMax(&g_winner[(size_t)u * 8 + z], i);
    }
}

// ---------------- ordered compaction of rows with cnt>=2 ----------------
__global__ void k_count(const int* __restrict__ cnt, int U) {
    __shared__ int s[256];
    int base = blockIdx.x * 1024;
    int c = 0;
    for (int t = threadIdx.x; t < 1024; t += 256) {
        int u = base + t;
        if (u < U && cnt[u] >= 2) c++;
    }
    s[threadIdx.x] = c;
    __syncthreads();
    for (int o = 128; o > 0; o >>= 1) {
        if (threadIdx.x < o) s[threadIdx.x] += s[threadIdx.x + o];
        __syncthreads();
    }
    if (threadIdx.x == 0) g_bsum[blockIdx.x] = s[0];
}

__global__ void k_scan2(int nb) {
    __shared__ int s[256];
    int t = threadIdx.x;
    int v = (t < nb) ? g_bsum[t] : 0;
    s[t] = v;
    __syncthreads();
    for (int o = 1; o < 256; o <<= 1) {
        int u = (t >= o) ? s[t - o] : 0;
        __syncthreads();
        s[t] += u;
        __syncthreads();
    }
    if (t < nb) g_bsum[t] = s[t] - v;   // exclusive
}

__global__ void k_compact(const int* __restrict__ cnt, int U) {
    __shared__ int s[256];
    int tid = threadIdx.x;
    int base = blockIdx.x * 1024 + tid * 4;
    int flags[4]; int c = 0;
    for (int q = 0; q < 4; q++) {
        int u = base + q;
        flags[q] = (u < U && cnt[u] >= 2) ? 1 : 0;
        c += flags[q];
    }
    s[tid] = c;
    __syncthreads();
    for (int o = 1; o < 256; o <<= 1) {
        int v = (tid >= o) ? s[tid - o] : 0;
        __syncthreads();
        s[tid] += v;
        __syncthreads();
    }
    int off = g_bsum[blockIdx.x] + s[tid] - c;
    for (int q = 0; q < 4; q++) {
        if (flags[q]) g_selrows[off++] = base + q;
    }
}

// ---------------- weight transpose: fp16 ----------------
__global__ void k_prepw(const float* __restrict__ W) {
    int i = blockIdx.x * 256 + threadIdx.x;   // 131072 total
    int n = i >> 9, k = i & 511;
    g_wt_h[i] = __float2half(W[(size_t)k * 256 + n]);
}

__global__ void k_prepw2(const float* __restrict__ W) {
    int i = blockIdx.x * 256 + threadIdx.x;   // 16384 total
    int n = i >> 8, k = i & 255;
    g_w2t_h[i] = __float2half(W[(size_t)k * 64 + n]);
}

// ---------------- fused per-row (warp-per-row): slot MLP + CBAM + flatten ----------------
__global__ void __launch_bounds__(256)
k_rows2(const float* __restrict__ vf,
        const float* __restrict__ w1, const float* __restrict__ b1,
        const float* __restrict__ w2g, const float* __restrict__ b2,
        const float* __restrict__ caw1, const float* __restrict__ caw2,
        const float* __restrict__ saconv, int M)
{
    __shared__ float sw1[160], sb1[32], sb2[64];
    __shared__ float scw1[512], scw2[512], sconv[16];
    __shared__ float sfeatw[8][40];
    __shared__ __align__(16) float shidw[8][8][32];

    const unsigned FULL = 0xffffffffu;
    int tid  = threadIdx.x;
    int wid  = tid >> 5;
    int lane = tid & 31;

    for (int i = tid; i < 160; i += 256) sw1[i] = w1[i];
    if (tid < 32) sb1[tid] = b1[tid];
    if (tid < 64) sb2[tid] = b2[tid];
    for (int i = tid; i < 512; i += 256) scw1[i] = caw1[i];
    for (int i = tid; i < 512; i += 256) scw2[i] = caw2[i];
    if (tid < 14) sconv[tid] = saconv[tid];

    float w2a[32], w2b[32];
#pragma unroll
    for (int k = 0; k < 32; k++) {
        w2a[k] = w2g[k * 64 + lane];
        w2b[k] = w2g[k * 64 + lane + 32];
    }
    __syncthreads();

    for (int r = 0; r < 8; r++) {
        int j = blockIdx.x * 64 + wid * 8 + r;
        if (j >= M) break;
        int u = g_selrows[j];
        int wv = (lane < 8) ? g_winner[(size_t)u * 8 + lane] : -1;

#pragma unroll
        for (int q = 0; q < 2; q++) {
            int t = lane + q * 32;
            int valid = (t < 40);
            int zz = valid ? (t / 5) : 0;
            int f  = t - zz * 5;
            int w = __shfl_sync(FULL, wv, zz);
            if (valid) sfeatw[wid][t] = (w >= 0) ? vf[(size_t)w * 5 + f] : 0.f;
        }
        __syncwarp();

#pragma unroll
        for (int z = 0; z < 8; z++) {
            float a = sb1[lane];
#pragma unroll
            for (int f = 0; f < 5; f++) a += sfeatw[wid][z * 5 + f] * sw1[f * 32 + lane];
            shidw[wid][z][lane] = fmaxf(a, 0.f);
        }
        __syncwarp();

        float x0[8], x1[8];
#pragma unroll
        for (int z = 0; z < 8; z++) {
            float a0 = sb2[lane], a1 = sb2[lane + 32];
            const float* hz = &shidw[wid][z][0];
#pragma unroll
            for (int k4 = 0; k4 < 8; k4++) {
                float4 h = *(const float4*)(hz + k4 * 4);
                a0 += h.x * w2a[k4 * 4] + h.y * w2a[k4 * 4 + 1] + h.z * w2a[k4 * 4 + 2] + h.w * w2a[k4 * 4 + 3];
                a1 += h.x * w2b[k4 * 4] + h.y * w2b[k4 * 4 + 1] + h.z * w2b[k4 * 4 + 2] + h.w * w2b[k4 * 4 + 3];
            }
            x0[z] = a0; x1[z] = a1;
        }

        float m0 = 0.f, m1 = 0.f, q0 = -3.4e38f, q1 = -3.4e38f;
#pragma unroll
        for (int z = 0; z < 8; z++) {
            m0 += x0[z]; m1 += x1[z];
            q0 = fmaxf(q0, x0[z]); q1 = fmaxf(q1, x1[z]);
        }
        m0 *= 0.125f; m1 *= 0.125f;

        float s8[8];
#pragma unroll
        for (int r8 = 0; r8 < 8; r8++) {
            float pm = m0 * scw1[lane * 8 + r8] + m1 * scw1[(lane + 32) * 8 + r8];
            float px = q0 * scw1[lane * 8 + r8] + q1 * scw1[(lane + 32) * 8 + r8];
#pragma unroll
            for (int o = 16; o > 0; o >>= 1) {
                pm += __shfl_xor_sync(FULL, pm, o);
                px += __shfl_xor_sync(FULL, px, o);
            }
            s8[r8] = fmaxf(pm, 0.f) + fmaxf(px, 0.f);
        }

        float a0 = 0.f, a1 = 0.f;
#pragma unroll
        for (int r8 = 0; r8 < 8; r8++) {
            a0 += s8[r8] * scw2[r8 * 64 + lane];
            a1 += s8[r8] * scw2[r8 * 64 + lane + 32];
        }
        float ca0 = 1.f / (1.f + expf(-a0));
        float ca1 = 1.f / (1.f + expf(-a1));
#pragma unroll
        for (int z = 0; z < 8; z++) { x0[z] *= ca0; x1[z] *= ca1; }

        float szm[8], szx[8];
#pragma unroll
        for (int z = 0; z < 8; z++) {
            float s = x0[z] + x1[z];
            float m = fmaxf(x0[z], x1[z]);
#pragma unroll
            for (int o = 16; o > 0; o >>= 1) {
                s += __shfl_xor_sync(FULL, s, o);
                m = fmaxf(m, __shfl_xor_sync(FULL, m, o));
            }
            szm[z] = s * (1.f / 64.f);
            szx[z] = m;
        }

        float sav = 0.f;
        if (lane < 8) {
            float acc = 0.f;
#pragma unroll
            for (int t = 0; t < 7; t++) {
                int p = lane + t - 3;
                if (p >= 0 && p < 8) acc += szm[p] * sconv[t] + szx[p] * sconv[7 + t];
            }
            sav = 1.f / (1.f + expf(-acc));
        }
        float sa[8];
#pragma unroll
        for (int z = 0; z < 8; z++) sa[z] = __shfl_sync(FULL, sav, z);

        size_t base = (size_t)j * 512;
        uint32_t ph[4];
#pragma unroll
        for (int z2 = 0; z2 < 4; z2++) {
            __half2 h2 = __floats2half2_rn(x0[2 * z2] * sa[2 * z2], x0[2 * z2 + 1] * sa[2 * z2 + 1]);
            ph[z2] = *(uint32_t*)&h2;
        }
        *(uint4*)&g_flat_h[base + lane * 8] = *(uint4*)ph;
#pragma unroll
        for (int z2 = 0; z2 < 4; z2++) {
            __half2 h2 = __floats2half2_rn(x1[2 * z2] * sa[2 * z2], x1[2 * z2 + 1] * sa[2 * z2 + 1]);
            ph[z2] = *(uint32_t*)&h2;
        }
        *(uint4*)&g_flat_h[base + (lane + 32) * 8] = *(uint4*)ph;
        __syncwarp();
    }
}

// ---------------- common mma macros ----------------
#define LDSM4(R0, R1, R2, R3, ADDR) \
    asm volatile("ldmatrix.sync.aligned.m8n8.x4.shared.b16 {%0,%1,%2,%3}, [%4];" \
                 : "=r"(R0), "=r"(R1), "=r"(R2), "=r"(R3) : "r"(ADDR))

#define MMA16816F16(D, A, B) \
    asm volatile("mma.sync.aligned.m16n8k16.row.col.f32.f16.f16.f32 " \
                 "{%0,%1,%2,%3}, {%4,%5,%6,%7}, {%8,%9}, {%0,%1,%2,%3};" \
                 : "+f"((D)[0]), "+f"((D)[1]), "+f"((D)[2]), "+f"((D)[3]) \
                 : "r"((A)[0]), "r"((A)[1]), "r"((A)[2]), "r"((A)[3]), \
                   "r"((B)[0]), "r"((B)[1]))

__device__ __forceinline__ void cp16(uint32_t saddr, const void* gaddr, uint32_t sz) {
    asm volatile("cp.async.cg.shared.global [%0], [%1], 16, %2;"
                 :: "r"(saddr), "l"(gaddr), "r"(sz));
}

// ---------------- GEMM1 (mma.sync fp16 single-pass) + fused bn1 stats ----------------
#define G1_PITCHB  144
#define G1_A_OFF   0
#define G1_B_OFF   18432
#define G1_STAGE   36864

__global__ void __launch_bounds__(256, 2)
k_gemm1_mma(int M) {
    extern __shared__ __align__(16) char dsm[];
    uint32_t sbase = smem_u32(dsm);
    const unsigned FULL = 0xffffffffu;

    int tid  = threadIdx.x;
    int lane = tid & 31;
    int wid  = tid >> 5;
    int wm = wid & 1;
    int wn = wid >> 1;
    int row0 = blockIdx.x * 128;
    int col0 = blockIdx.y * 128;

    int li_r  = tid >> 3;
    int li_c8 = tid & 7;

    float acc[4][4][4] = {};

    auto load_chunk = [&](int c) {
        uint32_t st = sbase + (uint32_t)(c & 1) * G1_STAGE;
#pragma unroll
        for (int it = 0; it < 4; it++) {
            int r = li_r + it * 32;
            int gr = row0 + r;
            uint32_t soff = (uint32_t)(r * G1_PITCHB + li_c8 * 16);
            size_t goff = (size_t)gr * 512 + c * 64 + li_c8 * 8;
            uint32_t sz = (gr < M) ? 16u : 0u;
            cp16(st + G1_A_OFF + soff, g_flat_h + goff, sz);
            int n = col0 + r;
            size_t boff = (size_t)n * 512 + c * 64 + li_c8 * 8;
            cp16(st + G1_B_OFF + soff, g_wt_h + boff, 16u);
        }
        asm volatile("cp.async.commit_group;");
    };

    load_chunk(0);

    uint32_t aRow  = (uint32_t)(wm * 64 + (lane & 15));
    uint32_t aColB = (uint32_t)((lane >> 4) * 16);
    uint32_t bRow  = (uint32_t)(wn * 32 + ((lane >> 4) & 1) * 8 + (lane & 7));
    uint32_t bColB = (uint32_t)(((lane >> 3) & 1) * 16);

    for (int c = 0; c < 8; c++) {
        if (c < 7) load_chunk(c + 1);
        if (c < 7) { asm volatile("cp.async.wait_group 1;"); }
        else       { asm volatile("cp.async.wait_group 0;"); }
        __syncthreads();

        uint32_t st = sbase + (uint32_t)(c & 1) * G1_STAGE;
#pragma unroll
        for (int kk = 0; kk < 4; kk++) {
            uint32_t kb = (uint32_t)(kk * 32);
            uint32_t ah[4][4];
#pragma unroll
            for (int mi = 0; mi < 4; mi++) {
                uint32_t ad = st + G1_A_OFF + (aRow + mi * 16) * G1_PITCHB + kb + aColB;
                LDSM4(ah[mi][0], ah[mi][1], ah[mi][2], ah[mi][3], ad);
            }
            uint32_t bh[4][2];
#pragma unroll
            for (int nh = 0; nh < 2; nh++) {
                uint32_t bd = st + G1_B_OFF + (bRow + nh * 16) * G1_PITCHB + kb + bColB;
                uint32_t t0, t1, t2, t3;
                LDSM4(t0, t1, t2, t3, bd);
                bh[nh * 2][0] = t0; bh[nh * 2][1] = t1;
                bh[nh * 2 + 1][0] = t2; bh[nh * 2 + 1][1] = t3;
            }
#pragma unroll
            for (int mi = 0; mi < 4; mi++) {
#pragma unroll
                for (int ni = 0; ni < 4; ni++) {
                    MMA16816F16(acc[mi][ni], ah[mi], bh[ni]);
                }
            }
        }
        __syncthreads();
    }

    // z1 stored as fp16
#pragma unroll
    for (int mi = 0; mi < 4; mi++) {
#pragma unroll
        for (int ni = 0; ni < 4; ni++) {
            int grow = row0 + wm * 64 + mi * 16 + (lane >> 2);
            int gcol = col0 + wn * 32 + ni * 8 + (lane & 3) * 2;
            if (grow < M) {
                __half2 h = __floats2half2_rn(acc[mi][ni][0], acc[mi][ni][1]);
                *(uint32_t*)(g_z1h + (size_t)grow * 256 + gcol) = *(uint32_t*)&h;
            }
            if (grow + 8 < M) {
                __half2 h = __floats2half2_rn(acc[mi][ni][2], acc[mi][ni][3]);
                *(uint32_t*)(g_z1h + (size_t)(grow + 8) * 256 + gcol) = *(uint32_t*)&h;
            }
        }
    }

#pragma unroll
    for (int ni = 0; ni < 4; ni++) {
#pragma unroll
        for (int jj = 0; jj < 2; jj++) {
            float s = 0.f, s2 = 0.f;
#pragma unroll
            for (int mi = 0; mi < 4; mi++) {
                float v0 = acc[mi][ni][jj], v1 = acc[mi][ni][jj + 2];
                s += v0 + v1; s2 += v0 * v0 + v1 * v1;
            }
#pragma unroll
            for (int o = 4; o <= 16; o <<= 1) {
                s  += __shfl_xor_sync(FULL, s, o);
                s2 += __shfl_xor_sync(FULL, s2, o);
            }
            if ((lane >> 2) == 0) {
                int col = col0 + wn * 32 + ni * 8 + (lane & 3) * 2 + jj;
                atomicAdd(&g_stats1[col], s);
                atomicAdd(&g_stats1[256 + col], s2);
            }
        }
    }
}

__global__ void k_bnp(const float* __restrict__ g, const float* __restrict__ b,
                      int C, float invM, int which) {
    int c = blockIdx.x * blockDim.x + threadIdx.x;
    if (c < C) {
        const float* st = which ? g_stats2 : g_stats1;
        float* sc = which ? g_bn2sc : g_bn1sc;
        float* sh = which ? g_bn2sh : g_bn1sh;
        float mu  = st[c] * invM;
        float var = st[C + c] * invM - mu * mu;
        float s = g[c] * rsqrtf(var + 0.001f);
        sc[c] = s;
        sh[c] = b[c] - mu * s;
    }
}

// ---------------- GEMM2 (mma.sync fp16 single-pass): out = relu(bn1(z1)) @ W2 + fused bn2 stats ----------------
#define G2_PITCHB  144
#define G2_A_OFF   0
#define G2_B_OFF   18432
#define G2_SMEM    27648

__global__ void __launch_bounds__(256, 2)
k_gemm2_mma(float* __restrict__ out, int M) {
    extern __shared__ __align__(16) char dsm2[];
    uint32_t sbase = smem_u32(dsm2);
    __shared__ float ss[128];
    const unsigned FULL = 0xffffffffu;

    int tid  = threadIdx.x;
    int lane = tid & 31;
    int wid  = tid >> 5;
    int row0 = blockIdx.x * 128;

    if (tid < 128) ss[tid] = 0.f;

    float acc[8][4] = {};

    uint32_t aRow  = (uint32_t)(wid * 16 + (lane & 15));
    uint32_t aColB = (uint32_t)((lane >> 4) * 16);
    uint32_t bRowB = (uint32_t)(((lane >> 4) & 1) * 8 + (lane & 7));
    uint32_t bColB = (uint32_t)(((lane >> 3) & 1) * 16);

    for (int c = 0; c < 4; c++) {
        __syncthreads();
        // ---- A: load z1 fp16 (16 cols per thread), bn1+relu in fp32, back to fp16 smem ----
        {
            int f4 = tid & 3;
            int colb = f4 * 16;   // 16 consecutive cols
#pragma unroll
            for (int half = 0; half < 2; half++) {
                int r = (tid >> 2) + half * 64;
                int gr = row0 + r;
                uint32_t hv[8] = {};
                if (gr < M) {
                    const uint4* src = (const uint4*)(g_z1h + (size_t)gr * 256 + c * 64 + colb);
                    *(uint4*)&hv[0] = src[0];
                    *(uint4*)&hv[4] = src[1];
                }
                uint32_t outp[8];
#pragma unroll
                for (int p = 0; p < 8; p++) {
                    __half2 h2 = *(__half2*)&hv[p];
                    float2 v = __half22float2(h2);
                    int col = c * 64 + colb + p * 2;
                    float vsc0 = g_bn1sc[col],     vsh0 = g_bn1sh[col];
                    float vsc1 = g_bn1sc[col + 1], vsh1 = g_bn1sh[col + 1];
                    float y0 = (gr < M) ? fmaxf(v.x * vsc0 + vsh0, 0.f) : 0.f;
                    float y1 = (gr < M) ? fmaxf(v.y * vsc1 + vsh1, 0.f) : 0.f;
                    __half2 o = __floats2half2_rn(y0, y1);
                    outp[p] = *(uint32_t*)&o;
                }
                uint32_t off = (uint32_t)(r * G2_PITCHB + colb * 2);
                *(uint4*)(dsm2 + G2_A_OFF + off)      = *(uint4*)&outp[0];
                *(uint4*)(dsm2 + G2_A_OFF + off + 16) = *(uint4*)&outp[4];
            }
        }
        // ---- B: copy w2t chunk (64 n x 64 k fp16) ----
        {
            int n = tid >> 2;
            int kg = (tid & 3) * 16;
            const uint4* gh = (const uint4*)(g_w2t_h + (size_t)n * 256 + c * 64 + kg);
            uint32_t off = (uint32_t)(n * G2_PITCHB + kg * 2);
            *(uint4*)(dsm2 + G2_B_OFF + off)      = gh[0];
            *(uint4*)(dsm2 + G2_B_OFF + off + 16) = gh[1];
        }
        __syncthreads();

#pragma unroll
        for (int kk = 0; kk < 4; kk++) {
            uint32_t kb = (uint32_t)(kk * 32);
            uint32_t ah[4];
            {
                uint32_t ad = sbase + G2_A_OFF + aRow * G2_PITCHB + kb + aColB;
                LDSM4(ah[0], ah[1], ah[2], ah[3], ad);
            }
            uint32_t bh[8][2];
#pragma unroll
            for (int nh = 0; nh < 4; nh++) {
                uint32_t bd = sbase + G2_B_OFF + (nh * 16 + bRowB) * G2_PITCHB + kb + bColB;
                uint32_t t0, t1, t2, t3;
                LDSM4(t0, t1, t2, t3, bd);
                bh[nh * 2][0] = t0; bh[nh * 2][1] = t1;
                bh[nh * 2 + 1][0] = t2; bh[nh * 2 + 1][1] = t3;
            }
#pragma unroll
            for (int ni = 0; ni < 8; ni++) {
                MMA16816F16(acc[ni], ah, bh[ni]);
            }
        }
    }

    int grow = row0 + wid * 16 + (lane >> 2);
#pragma unroll
    for (int ni = 0; ni < 8; ni++) {
        int gcol = ni * 8 + (lane & 3) * 2;
        if (grow < M)
            *(float2*)(out + (size_t)grow * 64 + gcol) = make_float2(acc[ni][0], acc[ni][1]);
        if (grow + 8 < M)
            *(float2*)(out + (size_t)(grow + 8) * 64 + gcol) = make_float2(acc[ni][2], acc[ni][3]);
    }

#pragma unroll
    for (int ni = 0; ni < 8; ni++) {
#pragma unroll
        for (int jj = 0; jj < 2; jj++) {
            float s = acc[ni][jj] + acc[ni][jj + 2];
            float s2 = acc[ni][jj] * acc[ni][jj] + acc[ni][jj + 2] * acc[ni][jj + 2];
#pragma unroll
            for (int o = 4; o <= 16; o <<= 1) {
                s  += __shfl_xor_sync(FULL, s, o);
                s2 += __shfl_xor_sync(FULL, s2, o);
            }
            if ((lane >> 2) == 0) {
                int col = ni * 8 + (lane & 3) * 2 + jj;
                atomicAdd(&ss[col], s);
                atomicAdd(&ss[64 + col], s2);
            }
        }
    }
    __syncthreads();
    if (tid < 128) atomicAdd(&g_stats2[tid], ss[tid]);
}

__global__ void k_final(float* __restrict__ out, int n) {
    int i = blockIdx.x * blockDim.x + threadIdx.x;
    if (i < n) {
        int c = i & 63;
        out[i] = fmaxf(out[i] * g_bn2sc[c] + g_bn2sh[c], 0.f);
    }
}

// ---------------- launcher ----------------
extern "C" void kernel_launch(void* const* d_in, const int* in_sizes, int n_in,
                              void* d_out, int out_size) {
    const float* vf      = (const float*)d_in[0];
    const int*   coords  = (const int*)d_in[1];
    const int*   inv     = (const int*)d_in[3];
    const int*   cnt     = (const int*)d_in[4];
    const float* up_w1   = (const float*)d_in[5];
    const float* up_b1   = (const float*)d_in[6];
    const float* up_w2   = (const float*)d_in[7];
    const float* up_b2   = (const float*)d_in[8];
    const float* ca_w1   = (const float*)d_in[9];
    const float* ca_w2   = (const float*)d_in[10];
    const float* sa_conv = (const float*)d_in[11];
    const float* bs_w1   = (const float*)d_in[12];
    const float* bn1_g   = (const float*)d_in[13];
    const float* bn1_b   = (const float*)d_in[14];
    const float* bs_w2   = (const float*)d_in[15];
    const float* bn2_g   = (const float*)d_in[16];
    const float* bn2_b   = (const float*)d_in[17];

    int Nv = in_sizes[0] / 5;
    int U  = in_sizes[2];
    int M  = out_size / 64;
    if (M <= 0) return;

    int nwin = U * 8;
    k_init<<<(nwin + 255) / 256, 256>>>(nwin);
    k_scatter<<<(Nv + 255) / 256, 256>>>(coords, inv, Nv);

    int NB = (U + 1023) / 1024;
    k_count<<<NB, 256>>>(cnt, U);
    k_scan2<<<1, 256>>>(NB);
    k_compact<<<NB, 256>>>(cnt, U);

    k_prepw<<<512, 256>>>(bs_w1);
    k_prepw2<<<64, 256>>>(bs_w2);
    k_rows2<<<(M + 63) / 64, 256>>>(vf, up_w1, up_b1, up_w2, up_b2,
                                    ca_w1, ca_w2, sa_conv, M);

    {
        int dynsmem = 2 * G1_STAGE;
        cudaFuncSetAttribute(k_gemm1_mma, cudaFuncAttributeMaxDynamicSharedMemorySize, dynsmem);
        dim3 g1((M + 127) / 128, 2);
        k_gemm1_mma<<<g1, 256, dynsmem>>>(M);
    }
    k_bnp<<<1, 256>>>(bn1_g, bn1_b, 256, 1.f / (float)M, 0);

    {
        cudaFuncSetAttribute(k_gemm2_mma, cudaFuncAttributeMaxDynamicSharedMemorySize, G2_SMEM);
        k_gemm2_mma<<<(M + 127) / 128, 256, G2_SMEM>>>((float*)d_out, M);
    }
    k_bnp<<<1, 64>>>(bn2_g, bn2_b, 64, 1.f / (float)M, 1);
    k_final<<<(M * 64 + 255) / 256, 256>>>((float*)d_out, M * 64);
}